// round 1
// baseline (speedup 1.0000x reference)
#include <cuda_runtime.h>
#include <math.h>

// vgae_decoder: out[e] = sigmoid( relu( relu(x[u]*x[v]) @ W1 + b1 ) @ W2 + b2 )
// for e in [0, 2E): first E edges from edge_index, next E from edge_index_neg.
//
// Tiling: 128 edges per block, 256 threads.
//   smem: W1 [128x128] (64KB) + H tile [128 x 132] (66KB)
//   GEMM: 8x8 register tile per thread (16 tx x 16 ty thread grid)
//   Fused epilogue: +b1, relu, dot W2, reduce across 16 tx, +b2, sigmoid.

#define TILE_E   128
#define NTHREADS 256
#define H_STRIDE 132   // 128 + 4 pad, keeps float4 alignment

__global__ void __launch_bounds__(NTHREADS, 1)
vgae_decoder_kernel(const float* __restrict__ x,
                    const float* __restrict__ W1,
                    const float* __restrict__ b1g,
                    const float* __restrict__ W2,
                    const float* __restrict__ b2g,
                    const int*   __restrict__ ei_pos,
                    const int*   __restrict__ ei_neg,
                    float*       __restrict__ out,
                    int E, int total)
{
    extern __shared__ float smem[];
    float* sW = smem;               // 128*128 floats, row-major [k][j]
    float* sH = smem + 128 * 128;   // 128 rows * H_STRIDE

    const int tid    = threadIdx.x;
    const int e_base = blockIdx.x * TILE_E;

    // ---- Load W1 into smem (16384 floats = 4096 float4) ----
    {
        const float4* w4 = (const float4*)W1;
        float4* s4 = (float4*)sW;
        #pragma unroll
        for (int i = tid; i < (128 * 128) / 4; i += NTHREADS)
            s4[i] = w4[i];
    }

    // ---- Build H tile: H[r][k] = relu(x[u][k] * x[v][k]) ----
    {
        const int warp = tid >> 5, lane = tid & 31;
        #pragma unroll
        for (int r = warp; r < TILE_E; r += NTHREADS / 32) {
            int e = e_base + r;
            float4 h4 = make_float4(0.f, 0.f, 0.f, 0.f);
            if (e < total) {
                const int* ei = ei_pos;
                int el = e;
                if (el >= E) { ei = ei_neg; el -= E; }
                int u = __ldg(ei + el);
                int v = __ldg(ei + el + E);
                float4 a = ((const float4*)(x + (size_t)u * 128))[lane];
                float4 b = ((const float4*)(x + (size_t)v * 128))[lane];
                h4.x = fmaxf(a.x * b.x, 0.f);
                h4.y = fmaxf(a.y * b.y, 0.f);
                h4.z = fmaxf(a.z * b.z, 0.f);
                h4.w = fmaxf(a.w * b.w, 0.f);
            }
            ((float4*)(sH + r * H_STRIDE))[lane] = h4;
        }
    }
    __syncthreads();

    // ---- GEMM: C[e][j] = sum_k H[e][k] * W1[k][j], 8x8 per thread ----
    const int tx = tid & 15;   // j-tile: columns tx*8 .. tx*8+7
    const int ty = tid >> 4;   // e-tile: rows    ty*8 .. ty*8+7

    float acc[8][8];
    #pragma unroll
    for (int i = 0; i < 8; ++i)
        #pragma unroll
        for (int j = 0; j < 8; ++j) acc[i][j] = 0.f;

    const float* hp = sH + ty * 8 * H_STRIDE;
    const float* wp = sW + tx * 8;

    #pragma unroll 8
    for (int k = 0; k < 128; ++k) {
        float a[8];
        #pragma unroll
        for (int i = 0; i < 8; ++i) a[i] = hp[i * H_STRIDE + k];
        float4 bv0 = *(const float4*)(wp + k * 128);
        float4 bv1 = *(const float4*)(wp + k * 128 + 4);
        float b[8] = {bv0.x, bv0.y, bv0.z, bv0.w, bv1.x, bv1.y, bv1.z, bv1.w};
        #pragma unroll
        for (int i = 0; i < 8; ++i)
            #pragma unroll
            for (int j = 0; j < 8; ++j)
                acc[i][j] = fmaf(a[i], b[j], acc[i][j]);
    }

    // ---- Fused epilogue: +b1, relu, dot with W2 (partial over 8 j's) ----
    float bias[8], w2r[8];
    #pragma unroll
    for (int j = 0; j < 8; ++j) {
        bias[j] = __ldg(b1g + tx * 8 + j);
        w2r[j]  = __ldg(W2  + tx * 8 + j);
    }
    float part[8];
    #pragma unroll
    for (int i = 0; i < 8; ++i) {
        float p = 0.f;
        #pragma unroll
        for (int j = 0; j < 8; ++j) {
            float y = fmaxf(acc[i][j] + bias[j], 0.f);
            p = fmaf(y, w2r[j], p);
        }
        part[i] = p;
    }

    // ---- Reduce the 16 tx-partials per edge, sigmoid, store ----
    __syncthreads();                 // done reading sH as H tile
    float* red = sH;                 // reuse: [128][16]
    #pragma unroll
    for (int i = 0; i < 8; ++i)
        red[(ty * 8 + i) * 16 + tx] = part[i];
    __syncthreads();

    if (tid < TILE_E) {
        int e = e_base + tid;
        if (e < total) {
            float s = 0.f;
            #pragma unroll
            for (int t = 0; t < 16; ++t) s += red[tid * 16 + t];
            s += __ldg(b2g);
            out[e] = 1.f / (1.f + expf(-s));
        }
    }
}

extern "C" void kernel_launch(void* const* d_in, const int* in_sizes, int n_in,
                              void* d_out, int out_size)
{
    const float* x  = (const float*)d_in[0];
    const float* W1 = (const float*)d_in[1];
    const float* b1 = (const float*)d_in[2];
    const float* W2 = (const float*)d_in[3];
    const float* b2 = (const float*)d_in[4];
    const int* eip  = (const int*)d_in[5];
    const int* ein  = (const int*)d_in[6];
    float* out = (float*)d_out;

    int E     = in_sizes[5] / 2;   // edge_index is [2, E]
    int total = out_size;          // 2E
    int blocks = (total + TILE_E - 1) / TILE_E;

    size_t smem = (size_t)(128 * 128 + 128 * H_STRIDE) * sizeof(float); // 133120 B
    cudaFuncSetAttribute(vgae_decoder_kernel,
                         cudaFuncAttributeMaxDynamicSharedMemorySize, (int)smem);
    vgae_decoder_kernel<<<blocks, NTHREADS, smem>>>(x, W1, b1, W2, b2,
                                                    eip, ein, out, E, total);
}

// round 2
// speedup vs baseline: 1.0153x; 1.0153x over previous
#include <cuda_runtime.h>
#include <math.h>

// vgae_decoder with packed-f32x2 GEMM:
// out[e] = sigmoid( relu( relu(x[u]*x[v]) @ W1 + b1 ) @ W2 + b2 )
//
// 128 edges per block, 256 threads.
//   smem: W1 [128x128] (64KB, row-major [k][j]) + H tile [128 x 132] (66KB)
//   GEMM: 8 rows x 8 cols per thread, cols as 4 packed j-pairs,
//         inner loop uses fma.rn.f32x2 (FFMA2) -> half the fma-pipe slots.
//   j-pair assignment strided: thread tx owns pairs p = tx, tx+16, tx+32, tx+48
//         (j = 2p, 2p+1) so the 4 LDS.64 b-loads are conflict-free.

#define TILE_E   128
#define NTHREADS 256
#define H_STRIDE 132

typedef unsigned long long u64;

__device__ __forceinline__ void ffma2(u64& d, u64 a, u64 b) {
    asm("fma.rn.f32x2 %0, %1, %2, %0;" : "+l"(d) : "l"(a), "l"(b));
}
__device__ __forceinline__ u64 dup2(float a) {
    u64 r; asm("mov.b64 %0, {%1, %1};" : "=l"(r) : "f"(a)); return r;
}
__device__ __forceinline__ float2 unpack2(u64 v) {
    float2 f; asm("mov.b64 {%0, %1}, %2;" : "=f"(f.x), "=f"(f.y) : "l"(v)); return f;
}

__global__ void __launch_bounds__(NTHREADS, 1)
vgae_decoder_kernel(const float* __restrict__ x,
                    const float* __restrict__ W1,
                    const float* __restrict__ b1g,
                    const float* __restrict__ W2,
                    const float* __restrict__ b2g,
                    const int*   __restrict__ ei_pos,
                    const int*   __restrict__ ei_neg,
                    float*       __restrict__ out,
                    int E, int total)
{
    extern __shared__ float smem[];
    float* sW = smem;               // 128*128, row-major [k][j]
    float* sH = smem + 128 * 128;   // 128 rows * H_STRIDE

    const int tid    = threadIdx.x;
    const int e_base = blockIdx.x * TILE_E;

    // ---- Load W1 into smem (coalesced float4) ----
    {
        const float4* w4 = (const float4*)W1;
        float4* s4 = (float4*)sW;
        #pragma unroll
        for (int i = tid; i < (128 * 128) / 4; i += NTHREADS)
            s4[i] = w4[i];
    }

    // ---- Build H tile: H[r][k] = relu(x[u][k] * x[v][k]) ----
    {
        const int warp = tid >> 5, lane = tid & 31;
        #pragma unroll
        for (int r = warp; r < TILE_E; r += NTHREADS / 32) {
            int e = e_base + r;
            float4 h4 = make_float4(0.f, 0.f, 0.f, 0.f);
            if (e < total) {
                const int* ei = ei_pos;
                int el = e;
                if (el >= E) { ei = ei_neg; el -= E; }
                int u = __ldg(ei + el);
                int v = __ldg(ei + el + E);
                float4 a = ((const float4*)(x + (size_t)u * 128))[lane];
                float4 b = ((const float4*)(x + (size_t)v * 128))[lane];
                h4.x = fmaxf(a.x * b.x, 0.f);
                h4.y = fmaxf(a.y * b.y, 0.f);
                h4.z = fmaxf(a.z * b.z, 0.f);
                h4.w = fmaxf(a.w * b.w, 0.f);
            }
            ((float4*)(sH + r * H_STRIDE))[lane] = h4;
        }
    }
    __syncthreads();

    // ---- GEMM: acc2[i][m] (+)= H[row_i][k] * (W1[k][2p], W1[k][2p+1]),
    //      p = tx + 16*m  (strided pair assignment, conflict-free LDS.64)
    const int tx = tid & 15;
    const int ty = tid >> 4;

    u64 acc2[8][4];
    #pragma unroll
    for (int i = 0; i < 8; ++i)
        #pragma unroll
        for (int m = 0; m < 4; ++m) acc2[i][m] = 0ULL;

    const float* hp = sH + ty * 8 * H_STRIDE;
    const float* wp = sW + tx * 2;   // + k*128 + m*32

    #pragma unroll 2
    for (int k = 0; k < 128; k += 4) {
        float4 av[8];
        #pragma unroll
        for (int i = 0; i < 8; ++i)
            av[i] = *(const float4*)(hp + i * H_STRIDE + k);

        #pragma unroll
        for (int kk = 0; kk < 4; ++kk) {
            u64 b2[4];
            const float* wk = wp + (k + kk) * 128;
            #pragma unroll
            for (int m = 0; m < 4; ++m)
                b2[m] = *(const u64*)(wk + m * 32);

            u64 a2[8];
            #pragma unroll
            for (int i = 0; i < 8; ++i) {
                float a = (kk == 0) ? av[i].x : (kk == 1) ? av[i].y
                        : (kk == 2) ? av[i].z : av[i].w;
                a2[i] = dup2(a);
            }
            #pragma unroll
            for (int i = 0; i < 8; ++i)
                #pragma unroll
                for (int m = 0; m < 4; ++m)
                    ffma2(acc2[i][m], a2[i], b2[m]);
        }
    }

    // ---- Fused epilogue: +b1, relu, dot with W2 over this thread's 8 j's ----
    float2 bias[4], w2r[4];
    #pragma unroll
    for (int m = 0; m < 4; ++m) {
        int j0 = (tx + 16 * m) * 2;
        bias[m] = make_float2(__ldg(b1g + j0), __ldg(b1g + j0 + 1));
        w2r[m]  = make_float2(__ldg(W2  + j0), __ldg(W2  + j0 + 1));
    }
    float part[8];
    #pragma unroll
    for (int i = 0; i < 8; ++i) {
        float p = 0.f;
        #pragma unroll
        for (int m = 0; m < 4; ++m) {
            float2 c = unpack2(acc2[i][m]);
            float y0 = fmaxf(c.x + bias[m].x, 0.f);
            float y1 = fmaxf(c.y + bias[m].y, 0.f);
            p = fmaf(y0, w2r[m].x, p);
            p = fmaf(y1, w2r[m].y, p);
        }
        part[i] = p;
    }

    // ---- Reduce 16 tx-partials per edge, sigmoid, store ----
    __syncthreads();
    float* red = sH;                 // reuse as [128][16]
    #pragma unroll
    for (int i = 0; i < 8; ++i)
        red[(ty * 8 + i) * 16 + tx] = part[i];
    __syncthreads();

    if (tid < TILE_E) {
        int e = e_base + tid;
        if (e < total) {
            float s = 0.f;
            #pragma unroll
            for (int t = 0; t < 16; ++t) s += red[tid * 16 + t];
            s += __ldg(b2g);
            out[e] = 1.f / (1.f + expf(-s));
        }
    }
}

extern "C" void kernel_launch(void* const* d_in, const int* in_sizes, int n_in,
                              void* d_out, int out_size)
{
    const float* x  = (const float*)d_in[0];
    const float* W1 = (const float*)d_in[1];
    const float* b1 = (const float*)d_in[2];
    const float* W2 = (const float*)d_in[3];
    const float* b2 = (const float*)d_in[4];
    const int* eip  = (const int*)d_in[5];
    const int* ein  = (const int*)d_in[6];
    float* out = (float*)d_out;

    int E     = in_sizes[5] / 2;   // edge_index is [2, E]
    int total = out_size;          // 2E
    int blocks = (total + TILE_E - 1) / TILE_E;

    size_t smem = (size_t)(128 * 128 + 128 * H_STRIDE) * sizeof(float); // 133120 B
    cudaFuncSetAttribute(vgae_decoder_kernel,
                         cudaFuncAttributeMaxDynamicSharedMemorySize, (int)smem);
    vgae_decoder_kernel<<<blocks, NTHREADS, smem>>>(x, W1, b1, W2, b2,
                                                    eip, ein, out, E, total);
}

// round 4
// speedup vs baseline: 2.1204x; 2.0885x over previous
#include <cuda_runtime.h>
#include <cuda_bf16.h>
#include <math.h>
#include <stdint.h>

typedef unsigned int u32;
typedef unsigned long long u64;

// ---------------------------------------------------------------------------
// vgae_decoder via legacy tensor-core mma.sync (bf16 3-term error split):
//   out[e] = sigmoid( relu( relu(x[u]*x[v]) @ W1 + b1 ) @ W2 + b2 )
// D = Ahi@Bhi + Ahi@Blo + Alo@Bhi  (fp32 accum), A = H tile, B = W1.
//
// Persistent grid (148 blocks, 256 thr). Per block:
//   smem: Bhi frag 32K | Blo frag 32K | Ahi 34816 | Alo 34816 | misc 2K
//   warp tile 32 (m) x 64 (n); mma.m16n8k16.
// ---------------------------------------------------------------------------

#define SM_BHI 0
#define SM_BLO 32768
#define SM_AHI 65536
#define SM_ALO (65536 + 34816)           // 100352
#define SM_MISC (65536 + 69632)          // 135168
#define SMEM_TOTAL (135168 + 2048)       // 137216
#define A_PITCH 272                      // bytes per H row (136 bf16)
#define NTHREADS 256

// B fragments of W1 (row-major [k][n]) in mma fragment order, hi/lo split.
// idx = ((kt*8 + nt/2)*32 + lane)*2 + (nt&1); u64 = {b0(lo32), b1(hi32)}
__device__ u64 g_Bhi[4096];
__device__ u64 g_Blo[4096];

__device__ __forceinline__ u32 pack_bf2(__nv_bfloat16 a, __nv_bfloat16 b) {
    __nv_bfloat162 t; t.x = a; t.y = b; return *(u32*)&t;
}

__global__ void prep_kernel(const float* __restrict__ W1) {
    int t = blockIdx.x * blockDim.x + threadIdx.x;   // 0..4095
    if (t >= 4096) return;
    int lane = t & 31, nt = (t >> 5) & 15, kt = t >> 9;
    int n  = nt * 8 + (lane >> 2);
    int k0 = kt * 16 + (lane & 3) * 2;

    float w[4] = { W1[(k0    ) * 128 + n], W1[(k0 + 1) * 128 + n],
                   W1[(k0 + 8) * 128 + n], W1[(k0 + 9) * 128 + n] };
    __nv_bfloat16 h[4], l[4];
    #pragma unroll
    for (int i = 0; i < 4; ++i) {
        h[i] = __float2bfloat16(w[i]);
        l[i] = __float2bfloat16(w[i] - __bfloat162float(h[i]));
    }
    u32 b0h = pack_bf2(h[0], h[1]), b1h = pack_bf2(h[2], h[3]);
    u32 b0l = pack_bf2(l[0], l[1]), b1l = pack_bf2(l[2], l[3]);
    int idx = ((kt * 8 + (nt >> 1)) * 32 + lane) * 2 + (nt & 1);
    g_Bhi[idx] = ((u64)b1h << 32) | b0h;
    g_Blo[idx] = ((u64)b1l << 32) | b0l;
}

__device__ __forceinline__ void mma_bf16(float* d, const u32* a, const u32* b) {
    asm volatile(
        "mma.sync.aligned.m16n8k16.row.col.f32.bf16.bf16.f32 "
        "{%0,%1,%2,%3}, {%4,%5,%6,%7}, {%8,%9}, {%0,%1,%2,%3};"
        : "+f"(d[0]), "+f"(d[1]), "+f"(d[2]), "+f"(d[3])
        : "r"(a[0]), "r"(a[1]), "r"(a[2]), "r"(a[3]), "r"(b[0]), "r"(b[1]));
}

__global__ void __launch_bounds__(NTHREADS, 1)
vgae_mma_kernel(const float* __restrict__ x,
                const float* __restrict__ b1g,
                const float* __restrict__ W2,
                const float* __restrict__ b2g,
                const int*   __restrict__ ei_pos,
                const int*   __restrict__ ei_neg,
                float*       __restrict__ out,
                int E, int total, int n_tiles)
{
    extern __shared__ char smem[];
    float* sB1  = (float*)(smem + SM_MISC);          // 128 f32
    float* sW2  = (float*)(smem + SM_MISC + 512);    // 128 f32
    float* sRed = (float*)(smem + SM_MISC + 1024);   // 128 x 2 f32

    const int tid  = threadIdx.x;
    const int wid  = tid >> 5;
    const int lane = tid & 31;
    const int wm   = wid & 3;        // m-strip: rows wm*32 .. +31
    const int wn   = wid >> 2;       // n-strip: cols wn*64 .. +63

    // ---- one-time: B fragments + bias/W2 into smem ----
    {
        u64* bh = (u64*)(smem + SM_BHI);
        u64* bl = (u64*)(smem + SM_BLO);
        #pragma unroll 4
        for (int i = tid; i < 4096; i += NTHREADS) {
            bh[i] = g_Bhi[i];
            bl[i] = g_Blo[i];
        }
        if (tid < 128) { sB1[tid] = b1g[tid]; sW2[tid] = W2[tid]; }
    }
    const float b2v = __ldg(b2g);
    __syncthreads();

    // fragment base addresses (byte offsets into smem)
    const u32 a_base = SM_AHI + (u32)(wm * 32 + (lane >> 2)) * A_PITCH
                              + (u32)(lane & 3) * 4;

    for (int tile = blockIdx.x; tile < n_tiles; tile += gridDim.x) {
        const int e_base = tile << 7;

        // ================= gather: H[r][k]=relu(x[u][k]*x[v][k]), split =====
        #pragma unroll 4
        for (int rr = 0; rr < 16; ++rr) {
            int r = wid * 16 + rr;
            int e = e_base + r;
            if (e < total) {
                const int* ei = ei_pos;
                int el = e;
                if (el >= E) { ei = ei_neg; el -= E; }
                int u = __ldg(ei + el);
                int v = __ldg(ei + el + E);
                float4 a = ((const float4*)(x + (size_t)u * 128))[lane];
                float4 b = ((const float4*)(x + (size_t)v * 128))[lane];
                float h0 = fmaxf(a.x * b.x, 0.f), h1 = fmaxf(a.y * b.y, 0.f);
                float h2 = fmaxf(a.z * b.z, 0.f), h3 = fmaxf(a.w * b.w, 0.f);
                __nv_bfloat16 e0 = __float2bfloat16(h0), e1 = __float2bfloat16(h1);
                __nv_bfloat16 e2 = __float2bfloat16(h2), e3 = __float2bfloat16(h3);
                u32 hi01 = pack_bf2(e0, e1), hi23 = pack_bf2(e2, e3);
                u32 lo01 = pack_bf2(__float2bfloat16(h0 - __bfloat162float(e0)),
                                    __float2bfloat16(h1 - __bfloat162float(e1)));
                u32 lo23 = pack_bf2(__float2bfloat16(h2 - __bfloat162float(e2)),
                                    __float2bfloat16(h3 - __bfloat162float(e3)));
                u32 off = (u32)r * A_PITCH + (u32)lane * 8;
                *(u64*)(smem + SM_AHI + off) = ((u64)hi23 << 32) | hi01;
                *(u64*)(smem + SM_ALO + off) = ((u64)lo23 << 32) | lo01;
            }
        }
        __syncthreads();

        // ================= GEMM: warp tile 32x64, K=128 =====================
        float acc[2][8][4];
        #pragma unroll
        for (int mt = 0; mt < 2; ++mt)
            #pragma unroll
            for (int nt = 0; nt < 8; ++nt)
                #pragma unroll
                for (int c = 0; c < 4; ++c) acc[mt][nt][c] = 0.f;

        #pragma unroll
        for (int kt = 0; kt < 8; ++kt) {
            const u32 ka = (u32)kt * 32;     // kt*16 cols * 2B

            u32 ah[2][4], al[2][4];
            #pragma unroll
            for (int mt = 0; mt < 2; ++mt) {
                u32 base = a_base + (u32)mt * (16 * A_PITCH) + ka;
                ah[mt][0] = *(const u32*)(smem + base);
                ah[mt][1] = *(const u32*)(smem + base + 8 * A_PITCH);
                ah[mt][2] = *(const u32*)(smem + base + 16);
                ah[mt][3] = *(const u32*)(smem + base + 8 * A_PITCH + 16);
                u32 baseL = base + (SM_ALO - SM_AHI);
                al[mt][0] = *(const u32*)(smem + baseL);
                al[mt][1] = *(const u32*)(smem + baseL + 8 * A_PITCH);
                al[mt][2] = *(const u32*)(smem + baseL + 16);
                al[mt][3] = *(const u32*)(smem + baseL + 8 * A_PITCH + 16);
            }

            u32 bh[8][2], bl[8][2];
            #pragma unroll
            for (int np = 0; np < 4; ++np) {
                u32 boff = (u32)(((kt * 8 + wn * 4 + np) * 32 + lane) * 16);
                uint4 qh = *(const uint4*)(smem + SM_BHI + boff);
                uint4 ql = *(const uint4*)(smem + SM_BLO + boff);
                bh[np*2][0] = qh.x; bh[np*2][1] = qh.y;
                bh[np*2+1][0] = qh.z; bh[np*2+1][1] = qh.w;
                bl[np*2][0] = ql.x; bl[np*2][1] = ql.y;
                bl[np*2+1][0] = ql.z; bl[np*2+1][1] = ql.w;
            }

            #pragma unroll
            for (int mt = 0; mt < 2; ++mt)
                #pragma unroll
                for (int nt = 0; nt < 8; ++nt)
                    mma_bf16(acc[mt][nt], ah[mt], bh[nt]);
            #pragma unroll
            for (int mt = 0; mt < 2; ++mt)
                #pragma unroll
                for (int nt = 0; nt < 8; ++nt)
                    mma_bf16(acc[mt][nt], ah[mt], bl[nt]);
            #pragma unroll
            for (int mt = 0; mt < 2; ++mt)
                #pragma unroll
                for (int nt = 0; nt < 8; ++nt)
                    mma_bf16(acc[mt][nt], al[mt], bh[nt]);
        }

        // ================= epilogue: +b1, relu, dot W2, reduce ==============
        #pragma unroll
        for (int mt = 0; mt < 2; ++mt) {
            float p0 = 0.f, p1 = 0.f;    // row halves: lane/4 and lane/4+8
            #pragma unroll
            for (int nt = 0; nt < 8; ++nt) {
                int n = wn * 64 + nt * 8 + (lane & 3) * 2;
                float bia0 = sB1[n], bia1 = sB1[n + 1];
                float w20  = sW2[n], w21  = sW2[n + 1];
                p0 = fmaf(fmaxf(acc[mt][nt][0] + bia0, 0.f), w20, p0);
                p0 = fmaf(fmaxf(acc[mt][nt][1] + bia1, 0.f), w21, p0);
                p1 = fmaf(fmaxf(acc[mt][nt][2] + bia0, 0.f), w20, p1);
                p1 = fmaf(fmaxf(acc[mt][nt][3] + bia1, 0.f), w21, p1);
            }
            p0 += __shfl_xor_sync(0xffffffffu, p0, 1);
            p0 += __shfl_xor_sync(0xffffffffu, p0, 2);
            p1 += __shfl_xor_sync(0xffffffffu, p1, 1);
            p1 += __shfl_xor_sync(0xffffffffu, p1, 2);
            if ((lane & 3) == 0) {
                int r0 = wm * 32 + mt * 16 + (lane >> 2);
                sRed[r0 * 2 + wn] = p0;
                sRed[(r0 + 8) * 2 + wn] = p1;
            }
        }
        __syncthreads();

        if (tid < 128) {
            int e = e_base + tid;
            if (e < total) {
                float s = sRed[tid * 2] + sRed[tid * 2 + 1] + b2v;
                out[e] = 1.f / (1.f + expf(-s));
            }
        }
        // safe to start next gather: all mma reads of A happened before the
        // sRed barrier; sRed readers finish before their own next gather-bar.
    }
}

// ---------------------------------------------------------------------------
extern "C" void kernel_launch(void* const* d_in, const int* in_sizes, int n_in,
                              void* d_out, int out_size)
{
    const float* x  = (const float*)d_in[0];
    const float* W1 = (const float*)d_in[1];
    const float* b1 = (const float*)d_in[2];
    const float* W2 = (const float*)d_in[3];
    const float* b2 = (const float*)d_in[4];
    const int* eip  = (const int*)d_in[5];
    const int* ein  = (const int*)d_in[6];
    float* out = (float*)d_out;

    int E       = in_sizes[5] / 2;
    int total   = out_size;
    int n_tiles = (total + 127) / 128;

    prep_kernel<<<16, 256>>>(W1);

    cudaFuncSetAttribute(vgae_mma_kernel,
                         cudaFuncAttributeMaxDynamicSharedMemorySize, SMEM_TOTAL);
    int grid = 148;
    if (grid > n_tiles) grid = n_tiles;
    vgae_mma_kernel<<<grid, NTHREADS, SMEM_TOTAL>>>(x, b1, W2, b2, eip, ein,
                                                    out, E, total, n_tiles);
}

// round 5
// speedup vs baseline: 3.1213x; 1.4721x over previous
#include <cuda_runtime.h>
#include <cuda_bf16.h>
#include <math.h>
#include <stdint.h>

typedef unsigned int u32;
typedef unsigned long long u64;

// ---------------------------------------------------------------------------
// vgae_decoder via mma.sync m16n8k16 bf16, 3-term error split:
//   D = Ahi@Bhi + Ahi@Blo + Alo@Bhi   (fp32 accum)
// Persistent 148 blocks x 512 threads, 256-edge tiles.
//   smem: Bhi 32K | Blo 32K | Ahi 68K | Alo 68K | misc
//   warp tile 32(m) x 64(n): 8 m-strips x 2 n-strips = 16 warps.
// ---------------------------------------------------------------------------

#define SM_BHI 0
#define SM_BLO 32768
#define SM_AHI 65536
#define A_BYTES (256 * 272)              // 69632
#define SM_ALO (SM_AHI + A_BYTES)        // 135168
#define SM_MISC (SM_ALO + A_BYTES)       // 204800
#define SMEM_TOTAL (SM_MISC + 3072)      // 207872
#define A_PITCH 272
#define NTHREADS 512
#define TILE_E 256

// B fragments of W1 in mma order, hi/lo split (see prep_kernel)
__device__ u64 g_Bhi[4096];
__device__ u64 g_Blo[4096];

__device__ __forceinline__ u32 pack_bf2(__nv_bfloat16 a, __nv_bfloat16 b) {
    __nv_bfloat162 t; t.x = a; t.y = b; return *(u32*)&t;
}

__global__ void prep_kernel(const float* __restrict__ W1) {
    int t = blockIdx.x * blockDim.x + threadIdx.x;   // 0..4095
    if (t >= 4096) return;
    int lane = t & 31, nt = (t >> 5) & 15, kt = t >> 9;
    int n  = nt * 8 + (lane >> 2);
    int k0 = kt * 16 + (lane & 3) * 2;

    float w[4] = { W1[(k0    ) * 128 + n], W1[(k0 + 1) * 128 + n],
                   W1[(k0 + 8) * 128 + n], W1[(k0 + 9) * 128 + n] };
    __nv_bfloat16 h[4], l[4];
    #pragma unroll
    for (int i = 0; i < 4; ++i) {
        h[i] = __float2bfloat16(w[i]);
        l[i] = __float2bfloat16(w[i] - __bfloat162float(h[i]));
    }
    int idx = ((kt * 8 + (nt >> 1)) * 32 + lane) * 2 + (nt & 1);
    g_Bhi[idx] = ((u64)pack_bf2(h[2], h[3]) << 32) | pack_bf2(h[0], h[1]);
    g_Blo[idx] = ((u64)pack_bf2(l[2], l[3]) << 32) | pack_bf2(l[0], l[1]);
}

__device__ __forceinline__ void mma_bf16(float* d, const u32* a, const u32* b) {
    asm volatile(
        "mma.sync.aligned.m16n8k16.row.col.f32.bf16.bf16.f32 "
        "{%0,%1,%2,%3}, {%4,%5,%6,%7}, {%8,%9}, {%0,%1,%2,%3};"
        : "+f"(d[0]), "+f"(d[1]), "+f"(d[2]), "+f"(d[3])
        : "r"(a[0]), "r"(a[1]), "r"(a[2]), "r"(a[3]), "r"(b[0]), "r"(b[1]));
}

__global__ void __launch_bounds__(NTHREADS, 1)
vgae_mma_kernel(const float* __restrict__ x,
                const float* __restrict__ b1g,
                const float* __restrict__ W2,
                const float* __restrict__ b2g,
                const int*   __restrict__ ei_pos,
                const int*   __restrict__ ei_neg,
                float*       __restrict__ out,
                int E, int total, int n_tiles)
{
    extern __shared__ char smem[];
    float* sB1  = (float*)(smem + SM_MISC);          // 128 f32
    float* sW2  = (float*)(smem + SM_MISC + 512);    // 128 f32
    float* sRed = (float*)(smem + SM_MISC + 1024);   // 256 x 2 f32

    const int tid  = threadIdx.x;
    const int wid  = tid >> 5;
    const int lane = tid & 31;
    const int wm   = wid & 7;        // m-strip: rows wm*32 .. +31
    const int wn   = wid >> 3;       // n-strip: cols wn*64 .. +63

    // ---- one-time: B fragments + bias/W2 into smem ----
    {
        u64* bh = (u64*)(smem + SM_BHI);
        u64* bl = (u64*)(smem + SM_BLO);
        #pragma unroll 4
        for (int i = tid; i < 4096; i += NTHREADS) {
            bh[i] = g_Bhi[i];
            bl[i] = g_Blo[i];
        }
        if (tid < 128) { sB1[tid] = b1g[tid]; sW2[tid] = W2[tid]; }
    }
    const float b2v = __ldg(b2g);
    __syncthreads();

    const u32 a_base = SM_AHI + (u32)(wm * 32 + (lane >> 2)) * A_PITCH
                              + (u32)(lane & 3) * 4;

    for (int tile = blockIdx.x; tile < n_tiles; tile += gridDim.x) {
        const int e_base = tile * TILE_E;

        // ============== gather: rows wid*16 .. +15 =========================
        {
            const int r0 = wid * 16;
            const int e0 = e_base + r0;
            // coalesced index load: lanes 0-15 -> u of rows 0-15,
            //                       lanes 16-31 -> v of rows 0-15
            const int* ei = ei_pos;
            int el0 = e0;
            if (el0 >= E) { ei = ei_neg; el0 -= E; }   // E%16==0: no straddle
            int myrow = lane & 15;
            int idxv = 0;
            if (e0 + myrow < total)
                idxv = __ldg(ei + el0 + myrow + ((lane >= 16) ? E : 0));

            #pragma unroll
            for (int rr = 0; rr < 16; ++rr) {
                int e = e0 + rr;
                if (e < total) {
                    int u = __shfl_sync(0xffffffffu, idxv, rr);
                    int v = __shfl_sync(0xffffffffu, idxv, rr + 16);
                    float4 a = ((const float4*)(x + (size_t)u * 128))[lane];
                    float4 b = ((const float4*)(x + (size_t)v * 128))[lane];
                    float h0 = fmaxf(a.x * b.x, 0.f), h1 = fmaxf(a.y * b.y, 0.f);
                    float h2 = fmaxf(a.z * b.z, 0.f), h3 = fmaxf(a.w * b.w, 0.f);
                    __nv_bfloat16 e0b = __float2bfloat16(h0), e1b = __float2bfloat16(h1);
                    __nv_bfloat16 e2b = __float2bfloat16(h2), e3b = __float2bfloat16(h3);
                    u32 hi01 = pack_bf2(e0b, e1b), hi23 = pack_bf2(e2b, e3b);
                    u32 lo01 = pack_bf2(__float2bfloat16(h0 - __bfloat162float(e0b)),
                                        __float2bfloat16(h1 - __bfloat162float(e1b)));
                    u32 lo23 = pack_bf2(__float2bfloat16(h2 - __bfloat162float(e2b)),
                                        __float2bfloat16(h3 - __bfloat162float(e3b)));
                    u32 off = (u32)(r0 + rr) * A_PITCH + (u32)lane * 8;
                    *(u64*)(smem + SM_AHI + off) = ((u64)hi23 << 32) | hi01;
                    *(u64*)(smem + SM_ALO + off) = ((u64)lo23 << 32) | lo01;
                }
            }
        }
        __syncthreads();

        // ============== GEMM: warp tile 32x64, K=128 =======================
        float acc[2][8][4];
        #pragma unroll
        for (int mt = 0; mt < 2; ++mt)
            #pragma unroll
            for (int nt = 0; nt < 8; ++nt)
                #pragma unroll
                for (int c = 0; c < 4; ++c) acc[mt][nt][c] = 0.f;

        #pragma unroll
        for (int kt = 0; kt < 8; ++kt) {
            const u32 ka = (u32)kt * 32;

            u32 ah[2][4], al[2][4];
            #pragma unroll
            for (int mt = 0; mt < 2; ++mt) {
                u32 base = a_base + (u32)mt * (16 * A_PITCH) + ka;
                ah[mt][0] = *(const u32*)(smem + base);
                ah[mt][1] = *(const u32*)(smem + base + 8 * A_PITCH);
                ah[mt][2] = *(const u32*)(smem + base + 16);
                ah[mt][3] = *(const u32*)(smem + base + 8 * A_PITCH + 16);
                u32 baseL = base + A_BYTES;
                al[mt][0] = *(const u32*)(smem + baseL);
                al[mt][1] = *(const u32*)(smem + baseL + 8 * A_PITCH);
                al[mt][2] = *(const u32*)(smem + baseL + 16);
                al[mt][3] = *(const u32*)(smem + baseL + 8 * A_PITCH + 16);
            }

            // process n in two halves of 4 tiles to cap live B registers
            #pragma unroll
            for (int half = 0; half < 2; ++half) {
                u32 bh[4][2], bl[4][2];
                #pragma unroll
                for (int np = 0; np < 2; ++np) {
                    u32 boff = (u32)(((kt * 8 + wn * 4 + half * 2 + np) * 32
                                      + lane) * 16);
                    uint4 qh = *(const uint4*)(smem + SM_BHI + boff);
                    uint4 ql = *(const uint4*)(smem + SM_BLO + boff);
                    bh[np*2][0] = qh.x; bh[np*2][1] = qh.y;
                    bh[np*2+1][0] = qh.z; bh[np*2+1][1] = qh.w;
                    bl[np*2][0] = ql.x; bl[np*2][1] = ql.y;
                    bl[np*2+1][0] = ql.z; bl[np*2+1][1] = ql.w;
                }
                #pragma unroll
                for (int mt = 0; mt < 2; ++mt)
                    #pragma unroll
                    for (int nt = 0; nt < 4; ++nt) {
                        float* a4 = acc[mt][half * 4 + nt];
                        mma_bf16(a4, ah[mt], bh[nt]);
                        mma_bf16(a4, ah[mt], bl[nt]);
                        mma_bf16(a4, al[mt], bh[nt]);
                    }
            }
        }

        // ============== epilogue: +b1, relu, dot W2, reduce ================
        #pragma unroll
        for (int mt = 0; mt < 2; ++mt) {
            float p0 = 0.f, p1 = 0.f;
            #pragma unroll
            for (int nt = 0; nt < 8; ++nt) {
                int n = wn * 64 + nt * 8 + (lane & 3) * 2;
                float bia0 = sB1[n], bia1 = sB1[n + 1];
                float w20  = sW2[n], w21  = sW2[n + 1];
                p0 = fmaf(fmaxf(acc[mt][nt][0] + bia0, 0.f), w20, p0);
                p0 = fmaf(fmaxf(acc[mt][nt][1] + bia1, 0.f), w21, p0);
                p1 = fmaf(fmaxf(acc[mt][nt][2] + bia0, 0.f), w20, p1);
                p1 = fmaf(fmaxf(acc[mt][nt][3] + bia1, 0.f), w21, p1);
            }
            p0 += __shfl_xor_sync(0xffffffffu, p0, 1);
            p0 += __shfl_xor_sync(0xffffffffu, p0, 2);
            p1 += __shfl_xor_sync(0xffffffffu, p1, 1);
            p1 += __shfl_xor_sync(0xffffffffu, p1, 2);
            if ((lane & 3) == 0) {
                int r0 = wm * 32 + mt * 16 + (lane >> 2);
                sRed[r0 * 2 + wn] = p0;
                sRed[(r0 + 8) * 2 + wn] = p1;
            }
        }
        __syncthreads();

        if (tid < TILE_E) {
            int e = e_base + tid;
            if (e < total) {
                float s = sRed[tid * 2] + sRed[tid * 2 + 1] + b2v;
                out[e] = 1.f / (1.f + expf(-s));
            }
        }
    }
}

// ---------------------------------------------------------------------------
extern "C" void kernel_launch(void* const* d_in, const int* in_sizes, int n_in,
                              void* d_out, int out_size)
{
    const float* x  = (const float*)d_in[0];
    const float* W1 = (const float*)d_in[1];
    const float* b1 = (const float*)d_in[2];
    const float* W2 = (const float*)d_in[3];
    const float* b2 = (const float*)d_in[4];
    const int* eip  = (const int*)d_in[5];
    const int* ein  = (const int*)d_in[6];
    float* out = (float*)d_out;

    int E       = in_sizes[5] / 2;
    int total   = out_size;
    int n_tiles = (total + TILE_E - 1) / TILE_E;

    prep_kernel<<<16, 256>>>(W1);

    cudaFuncSetAttribute(vgae_mma_kernel,
                         cudaFuncAttributeMaxDynamicSharedMemorySize, SMEM_TOTAL);
    int grid = 148;
    if (grid > n_tiles) grid = n_tiles;
    vgae_mma_kernel<<<grid, NTHREADS, SMEM_TOTAL>>>(x, b1, W2, b2, eip, ein,
                                                    out, E, total, n_tiles);
}

// round 6
// speedup vs baseline: 3.3872x; 1.0852x over previous
#include <cuda_runtime.h>
#include <cuda_bf16.h>
#include <math.h>
#include <stdint.h>

typedef unsigned int u32;
typedef unsigned long long u64;

// ---------------------------------------------------------------------------
// vgae_decoder, mma.sync m16n8k16 bf16, 3-term split, software-pipelined:
// while GEMM runs on buffer (it&1), next tile is gathered into buffer (~it&1).
// 148 persistent blocks x 512 threads, 128-edge tiles.
// smem: Bhi 32K | Blo 32K | A[2] x (hi 34816 + lo 34816) | misc
// warp tile 16(m) x 64(n): 8 m-strips x 2 n-strips.
// ---------------------------------------------------------------------------

#define A_PITCH 272
#define SM_BHI 0
#define SM_BLO 32768
#define SM_A   65536
#define A_HALF 34816                     // one hi or lo plane (128*272)
#define A_BUF  (2 * A_HALF)              // 69632
#define SM_MISC (SM_A + 2 * A_BUF)       // 204800
#define SMEM_TOTAL (SM_MISC + 2048)      // 206848
#define NTHREADS 512
#define TILE_E 128

__device__ u64 g_Bhi[4096];
__device__ u64 g_Blo[4096];

__device__ __forceinline__ u32 pack_bf2(__nv_bfloat16 a, __nv_bfloat16 b) {
    __nv_bfloat162 t; t.x = a; t.y = b; return *(u32*)&t;
}

__global__ void prep_kernel(const float* __restrict__ W1) {
    int t = blockIdx.x * blockDim.x + threadIdx.x;
    if (t >= 4096) return;
    int lane = t & 31, nt = (t >> 5) & 15, kt = t >> 9;
    int n  = nt * 8 + (lane >> 2);
    int k0 = kt * 16 + (lane & 3) * 2;
    float w[4] = { W1[(k0    ) * 128 + n], W1[(k0 + 1) * 128 + n],
                   W1[(k0 + 8) * 128 + n], W1[(k0 + 9) * 128 + n] };
    __nv_bfloat16 h[4], l[4];
    #pragma unroll
    for (int i = 0; i < 4; ++i) {
        h[i] = __float2bfloat16(w[i]);
        l[i] = __float2bfloat16(w[i] - __bfloat162float(h[i]));
    }
    int idx = ((kt * 8 + (nt >> 1)) * 32 + lane) * 2 + (nt & 1);
    g_Bhi[idx] = ((u64)pack_bf2(h[2], h[3]) << 32) | pack_bf2(h[0], h[1]);
    g_Blo[idx] = ((u64)pack_bf2(l[2], l[3]) << 32) | pack_bf2(l[0], l[1]);
}

__device__ __forceinline__ void mma_bf16(float* d, const u32* a, const u32* b) {
    asm volatile(
        "mma.sync.aligned.m16n8k16.row.col.f32.bf16.bf16.f32 "
        "{%0,%1,%2,%3}, {%4,%5,%6,%7}, {%8,%9}, {%0,%1,%2,%3};"
        : "+f"(d[0]), "+f"(d[1]), "+f"(d[2]), "+f"(d[3])
        : "r"(a[0]), "r"(a[1]), "r"(a[2]), "r"(a[3]), "r"(b[0]), "r"(b[1]));
}

// convert one H row (relu(a*b), bf16 hi/lo split) and store to smem
__device__ __forceinline__ void conv_store(char* smem, u32 hi_base, int row,
                                           int lane, float4 a, float4 b,
                                           bool valid) {
    u64 hp = 0, lp = 0;
    if (valid) {
        float h0 = fmaxf(a.x * b.x, 0.f), h1 = fmaxf(a.y * b.y, 0.f);
        float h2 = fmaxf(a.z * b.z, 0.f), h3 = fmaxf(a.w * b.w, 0.f);
        __nv_bfloat16 e0 = __float2bfloat16(h0), e1 = __float2bfloat16(h1);
        __nv_bfloat16 e2 = __float2bfloat16(h2), e3 = __float2bfloat16(h3);
        u32 hi01 = pack_bf2(e0, e1), hi23 = pack_bf2(e2, e3);
        u32 lo01 = pack_bf2(__float2bfloat16(h0 - __bfloat162float(e0)),
                            __float2bfloat16(h1 - __bfloat162float(e1)));
        u32 lo23 = pack_bf2(__float2bfloat16(h2 - __bfloat162float(e2)),
                            __float2bfloat16(h3 - __bfloat162float(e3)));
        hp = ((u64)hi23 << 32) | hi01;
        lp = ((u64)lo23 << 32) | lo01;
    }
    u32 off = (u32)row * A_PITCH + (u32)lane * 8;
    *(u64*)(smem + hi_base + off)          = hp;
    *(u64*)(smem + hi_base + A_HALF + off) = lp;
}

__global__ void __launch_bounds__(NTHREADS, 1)
vgae_mma_kernel(const float* __restrict__ x,
                const float* __restrict__ b1g,
                const float* __restrict__ W2,
                const float* __restrict__ b2g,
                const int*   __restrict__ ei_pos,
                const int*   __restrict__ ei_neg,
                float*       __restrict__ out,
                int E, int total, int n_tiles)
{
    extern __shared__ char smem[];
    float* sB1  = (float*)(smem + SM_MISC);
    float* sW2  = (float*)(smem + SM_MISC + 512);
    float* sRed = (float*)(smem + SM_MISC + 1024);   // 128 x 2

    const int tid  = threadIdx.x;
    const int wid  = tid >> 5;
    const int lane = tid & 31;
    const int wm   = wid & 7;        // 16-row m-strip
    const int wn   = wid >> 3;       // 64-col n-strip

    {
        u64* bh = (u64*)(smem + SM_BHI);
        u64* bl = (u64*)(smem + SM_BLO);
        #pragma unroll 4
        for (int i = tid; i < 4096; i += NTHREADS) {
            bh[i] = g_Bhi[i];
            bl[i] = g_Blo[i];
        }
        if (tid < 128) { sB1[tid] = b1g[tid]; sW2[tid] = W2[tid]; }
    }
    const float b2v = __ldg(b2g);

    const u32 a_frag0 = (u32)(wm * 16 + (lane >> 2)) * A_PITCH
                      + (u32)(lane & 3) * 4;
    const int r0 = wid * 8;          // this warp's gather rows

    // ---- index fetch helper (lanes 0-15): lane<8 -> u, lane>=8 -> v ----
    #define LOAD_IDX(T, IDXV) do {                                          \
        (IDXV) = 0;                                                         \
        int _e0 = (T) * TILE_E + r0;                                        \
        const int* _ei = ei_pos; int _el = _e0;                             \
        if (_el >= E) { _ei = ei_neg; _el -= E; }                           \
        if (lane < 16 && _e0 + (lane & 7) < total)                          \
            (IDXV) = __ldg(_ei + _el + (lane & 7) + ((lane >= 8) ? E : 0)); \
    } while (0)

    #define FETCH_ROW(IDXV, J, A4, B4, VAL, TBASE) do {                     \
        (VAL) = ((TBASE) + r0 + (J)) < total;                               \
        int _u = __shfl_sync(0xffffffffu, (IDXV), (J));                     \
        int _v = __shfl_sync(0xffffffffu, (IDXV), (J) + 8);                 \
        (A4) = ((const float4*)(x + (size_t)_u * 128))[lane];               \
        (B4) = ((const float4*)(x + (size_t)_v * 128))[lane];               \
    } while (0)

    // ---- prologue: gather first tile into buffer 0 ----
    {
        int tile0 = blockIdx.x;
        int tbase = tile0 * TILE_E;
        int idxv; LOAD_IDX(tile0, idxv);
        #pragma unroll
        for (int j = 0; j < 8; ++j) {
            float4 a4, b4; bool val;
            FETCH_ROW(idxv, j, a4, b4, val, tbase);
            conv_store(smem, SM_A, r0 + j, lane, a4, b4, val);
        }
    }
    __syncthreads();

    int it = 0;
    for (int tile = blockIdx.x; tile < n_tiles; tile += gridDim.x, ++it) {
        const int cur = it & 1;
        const u32 aHi = SM_A + (u32)cur * A_BUF;
        const u32 nHi = SM_A + (u32)(cur ^ 1) * A_BUF;
        const u32 a_cur = aHi + a_frag0;
        const int e_base = tile * TILE_E;

        const int tile_nx = tile + gridDim.x;
        const bool have_nx = tile_nx < n_tiles;
        const int nbase = tile_nx * TILE_E;

        // (1) next-tile index load, in flight under GEMM
        int idxv = 0;
        if (have_nx) LOAD_IDX(tile_nx, idxv);

        float acc[8][4];
        #pragma unroll
        for (int nt = 0; nt < 8; ++nt)
            #pragma unroll
            for (int c = 0; c < 4; ++c) acc[nt][c] = 0.f;

        #define KT_STEP(KT) do {                                            \
            u32 _b = a_cur + (u32)(KT) * 32;                                \
            u32 _ah[4], _al[4];                                             \
            _ah[0] = *(const u32*)(smem + _b);                              \
            _ah[1] = *(const u32*)(smem + _b + 8 * A_PITCH);                \
            _ah[2] = *(const u32*)(smem + _b + 16);                         \
            _ah[3] = *(const u32*)(smem + _b + 8 * A_PITCH + 16);           \
            _al[0] = *(const u32*)(smem + _b + A_HALF);                     \
            _al[1] = *(const u32*)(smem + _b + A_HALF + 8 * A_PITCH);       \
            _al[2] = *(const u32*)(smem + _b + A_HALF + 16);                \
            _al[3] = *(const u32*)(smem + _b + A_HALF + 8 * A_PITCH + 16);  \
            _Pragma("unroll")                                               \
            for (int half = 0; half < 2; ++half) {                          \
                u32 bh[4][2], bl[4][2];                                     \
                _Pragma("unroll")                                           \
                for (int np = 0; np < 2; ++np) {                            \
                    u32 boff = (u32)((((KT) * 8 + wn * 4 + half * 2 + np)   \
                                      * 32 + lane) * 16);                   \
                    uint4 qh = *(const uint4*)(smem + SM_BHI + boff);       \
                    uint4 ql = *(const uint4*)(smem + SM_BLO + boff);       \
                    bh[np*2][0] = qh.x; bh[np*2][1] = qh.y;                 \
                    bh[np*2+1][0] = qh.z; bh[np*2+1][1] = qh.w;             \
                    bl[np*2][0] = ql.x; bl[np*2][1] = ql.y;                 \
                    bl[np*2+1][0] = ql.z; bl[np*2+1][1] = ql.w;             \
                }                                                           \
                _Pragma("unroll")                                           \
                for (int nt = 0; nt < 4; ++nt) {                            \
                    float* a4 = acc[half * 4 + nt];                         \
                    mma_bf16(a4, _ah, bh[nt]);                              \
                    mma_bf16(a4, _ah, bl[nt]);                              \
                    mma_bf16(a4, _al, bh[nt]);                              \
                }                                                           \
            }                                                               \
        } while (0)

        // (2) GEMM kt 0-1 (covers index-load latency)
        KT_STEP(0); KT_STEP(1);

        // (3) prefetch next-tile rows 0-3
        float4 xa0, xb0, xa1, xb1, xa2, xb2, xa3, xb3;
        bool v0 = false, v1 = false, v2 = false, v3 = false;
        if (have_nx) {
            FETCH_ROW(idxv, 0, xa0, xb0, v0, nbase);
            FETCH_ROW(idxv, 1, xa1, xb1, v1, nbase);
            FETCH_ROW(idxv, 2, xa2, xb2, v2, nbase);
            FETCH_ROW(idxv, 3, xa3, xb3, v3, nbase);
        }

        // (4) GEMM kt 2-5
        KT_STEP(2); KT_STEP(3); KT_STEP(4); KT_STEP(5);

        // (5) convert rows 0-3, prefetch rows 4-7
        float4 xa4, xb4, xa5, xb5, xa6, xb6, xa7, xb7;
        bool v4 = false, v5 = false, v6 = false, v7 = false;
        if (have_nx) {
            conv_store(smem, nHi, r0 + 0, lane, xa0, xb0, v0);
            conv_store(smem, nHi, r0 + 1, lane, xa1, xb1, v1);
            conv_store(smem, nHi, r0 + 2, lane, xa2, xb2, v2);
            conv_store(smem, nHi, r0 + 3, lane, xa3, xb3, v3);
            FETCH_ROW(idxv, 4, xa4, xb4, v4, nbase);
            FETCH_ROW(idxv, 5, xa5, xb5, v5, nbase);
            FETCH_ROW(idxv, 6, xa6, xb6, v6, nbase);
            FETCH_ROW(idxv, 7, xa7, xb7, v7, nbase);
        }

        // (6) GEMM kt 6-7
        KT_STEP(6); KT_STEP(7);

        // (7) convert rows 4-7
        if (have_nx) {
            conv_store(smem, nHi, r0 + 4, lane, xa4, xb4, v4);
            conv_store(smem, nHi, r0 + 5, lane, xa5, xb5, v5);
            conv_store(smem, nHi, r0 + 6, lane, xa6, xb6, v6);
            conv_store(smem, nHi, r0 + 7, lane, xa7, xb7, v7);
        }
        #undef KT_STEP

        // (8) epilogue: +b1, relu, dot W2, reduce over lane&3, stash
        {
            float p0 = 0.f, p1 = 0.f;
            #pragma unroll
            for (int nt = 0; nt < 8; ++nt) {
                int n = wn * 64 + nt * 8 + (lane & 3) * 2;
                float bia0 = sB1[n], bia1 = sB1[n + 1];
                float w20  = sW2[n], w21  = sW2[n + 1];
                p0 = fmaf(fmaxf(acc[nt][0] + bia0, 0.f), w20, p0);
                p0 = fmaf(fmaxf(acc[nt][1] + bia1, 0.f), w21, p0);
                p1 = fmaf(fmaxf(acc[nt][2] + bia0, 0.f), w20, p1);
                p1 = fmaf(fmaxf(acc[nt][3] + bia1, 0.f), w21, p1);
            }
            p0 += __shfl_xor_sync(0xffffffffu, p0, 1);
            p0 += __shfl_xor_sync(0xffffffffu, p0, 2);
            p1 += __shfl_xor_sync(0xffffffffu, p1, 1);
            p1 += __shfl_xor_sync(0xffffffffu, p1, 2);
            if ((lane & 3) == 0) {
                int rr = wm * 16 + (lane >> 2);
                sRed[rr * 2 + wn] = p0;
                sRed[(rr + 8) * 2 + wn] = p1;
            }
        }
        __syncthreads();   // next-buffer gather + sRed complete

        if (tid < TILE_E) {
            int e = e_base + tid;
            if (e < total) {
                float s = sRed[tid * 2] + sRed[tid * 2 + 1] + b2v;
                out[e] = 1.f / (1.f + expf(-s));
            }
        }
        __syncthreads();   // out-reads of sRed done before next epilogue
    }
    #undef LOAD_IDX
    #undef FETCH_ROW
}

// ---------------------------------------------------------------------------
extern "C" void kernel_launch(void* const* d_in, const int* in_sizes, int n_in,
                              void* d_out, int out_size)
{
    const float* x  = (const float*)d_in[0];
    const float* W1 = (const float*)d_in[1];
    const float* b1 = (const float*)d_in[2];
    const float* W2 = (const float*)d_in[3];
    const float* b2 = (const float*)d_in[4];
    const int* eip  = (const int*)d_in[5];
    const int* ein  = (const int*)d_in[6];
    float* out = (float*)d_out;

    int E       = in_sizes[5] / 2;
    int total   = out_size;
    int n_tiles = (total + TILE_E - 1) / TILE_E;

    prep_kernel<<<16, 256>>>(W1);

    cudaFuncSetAttribute(vgae_mma_kernel,
                         cudaFuncAttributeMaxDynamicSharedMemorySize, SMEM_TOTAL);
    int grid = 148;
    if (grid > n_tiles) grid = n_tiles;
    vgae_mma_kernel<<<grid, NTHREADS, SMEM_TOTAL>>>(x, b1, W2, b2, eip, ein,
                                                    out, E, total, n_tiles);
}

// round 7
// speedup vs baseline: 4.3773x; 1.2923x over previous
#include <cuda_runtime.h>
#include <cuda_fp16.h>
#include <math.h>
#include <stdint.h>

typedef unsigned int u32;
typedef unsigned long long u64;

// ---------------------------------------------------------------------------
// vgae_decoder, mma.sync m16n8k16 fp16 (f32 accum), 2-term A split:
//   D = Ahi@B + Alo@B,  B = fp16(W1)  (residual ~2^-11, well under 1e-3)
// 148 persistent blocks x 512 threads, 128-edge tiles, double-buffered A.
// smem: B 32K | A[2] x (hi 34816 + lo 34816) | misc
// 16 warps: 4 m-strips (32 rows) x 4 n-strips (32 cols), warp tile 32x32.
// ---------------------------------------------------------------------------

#define A_PITCH 272
#define SM_B   0
#define SM_A   32768
#define A_HALF 34816
#define A_BUF  (2 * A_HALF)              // 69632
#define SM_MISC (SM_A + 2 * A_BUF)       // 172032
#define SMEM_TOTAL (SM_MISC + 3072)      // 175104
#define NTHREADS 512
#define TILE_E 128

__device__ u64 g_Bh[4096];   // fp16 W1 fragments, mma order

__device__ __forceinline__ u32 pack_hf2(__half a, __half b) {
    __half2 t; t.x = a; t.y = b; return *(u32*)&t;
}
__device__ __forceinline__ u32 smem_u32(const void* p) {
    u32 a; asm("{ .reg .u64 t; cvta.to.shared.u64 t, %1; cvt.u32.u64 %0, t; }"
               : "=r"(a) : "l"(p)); return a;
}
__device__ __forceinline__ void ldmatrix_x4(u32* r, u32 saddr) {
    asm volatile("ldmatrix.sync.aligned.m8n8.x4.shared.b16 {%0,%1,%2,%3}, [%4];"
                 : "=r"(r[0]), "=r"(r[1]), "=r"(r[2]), "=r"(r[3]) : "r"(saddr));
}
__device__ __forceinline__ void mma_fp16(float* d, const u32* a, const u32* b) {
    asm volatile(
        "mma.sync.aligned.m16n8k16.row.col.f32.f16.f16.f32 "
        "{%0,%1,%2,%3}, {%4,%5,%6,%7}, {%8,%9}, {%0,%1,%2,%3};"
        : "+f"(d[0]), "+f"(d[1]), "+f"(d[2]), "+f"(d[3])
        : "r"(a[0]), "r"(a[1]), "r"(a[2]), "r"(a[3]), "r"(b[0]), "r"(b[1]));
}

__global__ void prep_kernel(const float* __restrict__ W1) {
    int t = blockIdx.x * blockDim.x + threadIdx.x;
    if (t >= 4096) return;
    int lane = t & 31, nt = (t >> 5) & 15, kt = t >> 9;
    int n  = nt * 8 + (lane >> 2);
    int k0 = kt * 16 + (lane & 3) * 2;
    __half h0 = __float2half(W1[(k0    ) * 128 + n]);
    __half h1 = __float2half(W1[(k0 + 1) * 128 + n]);
    __half h2 = __float2half(W1[(k0 + 8) * 128 + n]);
    __half h3 = __float2half(W1[(k0 + 9) * 128 + n]);
    int idx = ((kt * 8 + (nt >> 1)) * 32 + lane) * 2 + (nt & 1);
    g_Bh[idx] = ((u64)pack_hf2(h2, h3) << 32) | pack_hf2(h0, h1);
}

// convert one H row (relu(a*b), fp16 hi/lo split of A) and store to smem
__device__ __forceinline__ void conv_store(char* smem, u32 hi_base, int row,
                                           int lane, float4 a, float4 b,
                                           bool valid) {
    u64 hp = 0, lp = 0;
    if (valid) {
        float h0 = fmaxf(a.x * b.x, 0.f), h1 = fmaxf(a.y * b.y, 0.f);
        float h2 = fmaxf(a.z * b.z, 0.f), h3 = fmaxf(a.w * b.w, 0.f);
        __half e0 = __float2half(h0), e1 = __float2half(h1);
        __half e2 = __float2half(h2), e3 = __float2half(h3);
        u32 hi01 = pack_hf2(e0, e1), hi23 = pack_hf2(e2, e3);
        u32 lo01 = pack_hf2(__float2half(h0 - __half2float(e0)),
                            __float2half(h1 - __half2float(e1)));
        u32 lo23 = pack_hf2(__float2half(h2 - __half2float(e2)),
                            __float2half(h3 - __half2float(e3)));
        hp = ((u64)hi23 << 32) | hi01;
        lp = ((u64)lo23 << 32) | lo01;
    }
    u32 off = (u32)row * A_PITCH + (u32)lane * 8;
    *(u64*)(smem + hi_base + off)          = hp;
    *(u64*)(smem + hi_base + A_HALF + off) = lp;
}

__global__ void __launch_bounds__(NTHREADS, 1)
vgae_mma_kernel(const float* __restrict__ x,
                const float* __restrict__ b1g,
                const float* __restrict__ W2,
                const float* __restrict__ b2g,
                const int*   __restrict__ ei_pos,
                const int*   __restrict__ ei_neg,
                float*       __restrict__ out,
                int E, int total, int n_tiles)
{
    extern __shared__ char smem[];
    float* sB1  = (float*)(smem + SM_MISC);
    float* sW2  = (float*)(smem + SM_MISC + 512);
    float* sRed = (float*)(smem + SM_MISC + 1024);   // 128 x 4

    const int tid  = threadIdx.x;
    const int wid  = tid >> 5;
    const int lane = tid & 31;
    const int wm   = wid & 3;        // 32-row m-strip
    const int wn   = wid >> 2;       // 32-col n-strip
    const u32 sbase = smem_u32(smem);

    {
        u64* bh = (u64*)(smem + SM_B);
        #pragma unroll 4
        for (int i = tid; i < 4096; i += NTHREADS) bh[i] = g_Bh[i];
        if (tid < 128) { sB1[tid] = b1g[tid]; sW2[tid] = W2[tid]; }
    }
    const float b2v = __ldg(b2g);

    // ldmatrix lane address pattern within a 16x16 A block
    const u32 a_lm0 = (u32)(wm * 32 + (lane & 15)) * A_PITCH
                    + (u32)(lane >> 4) * 16;
    const int r0 = wid * 8;          // this warp's gather rows

    #define LOAD_IDX(T, IDXV) do {                                          \
        (IDXV) = 0;                                                         \
        int _e0 = (T) * TILE_E + r0;                                        \
        const int* _ei = ei_pos; int _el = _e0;                             \
        if (_el >= E) { _ei = ei_neg; _el -= E; }                           \
        if (lane < 16 && _e0 + (lane & 7) < total)                          \
            (IDXV) = __ldg(_ei + _el + (lane & 7) + ((lane >= 8) ? E : 0)); \
    } while (0)

    #define FETCH_ROW(IDXV, J, A4, B4, VAL, TBASE) do {                     \
        (VAL) = ((TBASE) + r0 + (J)) < total;                               \
        int _u = __shfl_sync(0xffffffffu, (IDXV), (J));                     \
        int _v = __shfl_sync(0xffffffffu, (IDXV), (J) + 8);                 \
        (A4) = ((const float4*)(x + (size_t)_u * 128))[lane];               \
        (B4) = ((const float4*)(x + (size_t)_v * 128))[lane];               \
    } while (0)

    // ---- prologue: gather first tile into buffer 0 ----
    {
        int tile0 = blockIdx.x;
        int tbase = tile0 * TILE_E;
        int idxv; LOAD_IDX(tile0, idxv);
        #pragma unroll
        for (int j = 0; j < 8; ++j) {
            float4 a4, b4; bool val;
            FETCH_ROW(idxv, j, a4, b4, val, tbase);
            conv_store(smem, SM_A, r0 + j, lane, a4, b4, val);
        }
    }
    __syncthreads();

    int it = 0;
    for (int tile = blockIdx.x; tile < n_tiles; tile += gridDim.x, ++it) {
        const int cur = it & 1;
        const u32 aHi = SM_A + (u32)cur * A_BUF;
        const u32 nHi = SM_A + (u32)(cur ^ 1) * A_BUF;
        const u32 a_lm = sbase + aHi + a_lm0;   // hw shared address
        const int e_base = tile * TILE_E;

        const int tile_nx = tile + gridDim.x;
        const bool have_nx = tile_nx < n_tiles;
        const int nbase = tile_nx * TILE_E;

        int idxv = 0;
        if (have_nx) LOAD_IDX(tile_nx, idxv);

        float acc[2][4][4];
        #pragma unroll
        for (int mf = 0; mf < 2; ++mf)
            #pragma unroll
            for (int nt = 0; nt < 4; ++nt)
                #pragma unroll
                for (int c = 0; c < 4; ++c) acc[mf][nt][c] = 0.f;

        #define KT_STEP(KT) do {                                            \
            u32 ah[2][4], al[2][4];                                         \
            _Pragma("unroll")                                               \
            for (int mf = 0; mf < 2; ++mf) {                                \
                u32 ad = a_lm + (u32)mf * (16 * A_PITCH) + (u32)(KT) * 32;  \
                ldmatrix_x4(ah[mf], ad);                                    \
                ldmatrix_x4(al[mf], ad + A_HALF);                           \
            }                                                               \
            u32 bq[4][2];                                                   \
            _Pragma("unroll")                                               \
            for (int np = 0; np < 2; ++np) {                                \
                u32 boff = (u32)((((KT) * 8 + wn * 2 + np) * 32 + lane)     \
                                 * 16);                                     \
                uint4 q = *(const uint4*)(smem + SM_B + boff);              \
                bq[np*2][0] = q.x; bq[np*2][1] = q.y;                       \
                bq[np*2+1][0] = q.z; bq[np*2+1][1] = q.w;                   \
            }                                                               \
            _Pragma("unroll")                                               \
            for (int mf = 0; mf < 2; ++mf)                                  \
                _Pragma("unroll")                                           \
                for (int nt = 0; nt < 4; ++nt) {                            \
                    mma_fp16(acc[mf][nt], ah[mf], bq[nt]);                  \
                    mma_fp16(acc[mf][nt], al[mf], bq[nt]);                  \
                }                                                           \
        } while (0)

        KT_STEP(0); KT_STEP(1);

        float4 xa0, xb0, xa1, xb1, xa2, xb2, xa3, xb3;
        bool v0 = false, v1 = false, v2 = false, v3 = false;
        if (have_nx) {
            FETCH_ROW(idxv, 0, xa0, xb0, v0, nbase);
            FETCH_ROW(idxv, 1, xa1, xb1, v1, nbase);
            FETCH_ROW(idxv, 2, xa2, xb2, v2, nbase);
            FETCH_ROW(idxv, 3, xa3, xb3, v3, nbase);
        }

        KT_STEP(2); KT_STEP(3); KT_STEP(4); KT_STEP(5);

        float4 xa4, xb4, xa5, xb5, xa6, xb6, xa7, xb7;
        bool v4 = false, v5 = false, v6 = false, v7 = false;
        if (have_nx) {
            conv_store(smem, nHi, r0 + 0, lane, xa0, xb0, v0);
            conv_store(smem, nHi, r0 + 1, lane, xa1, xb1, v1);
            conv_store(smem, nHi, r0 + 2, lane, xa2, xb2, v2);
            conv_store(smem, nHi, r0 + 3, lane, xa3, xb3, v3);
            FETCH_ROW(idxv, 4, xa4, xb4, v4, nbase);
            FETCH_ROW(idxv, 5, xa5, xb5, v5, nbase);
            FETCH_ROW(idxv, 6, xa6, xb6, v6, nbase);
            FETCH_ROW(idxv, 7, xa7, xb7, v7, nbase);
        }

        KT_STEP(6); KT_STEP(7);

        if (have_nx) {
            conv_store(smem, nHi, r0 + 4, lane, xa4, xb4, v4);
            conv_store(smem, nHi, r0 + 5, lane, xa5, xb5, v5);
            conv_store(smem, nHi, r0 + 6, lane, xa6, xb6, v6);
            conv_store(smem, nHi, r0 + 7, lane, xa7, xb7, v7);
        }
        #undef KT_STEP

        // epilogue: +b1, relu, dot W2, reduce over lane&3
        #pragma unroll
        for (int mf = 0; mf < 2; ++mf) {
            float p0 = 0.f, p1 = 0.f;
            #pragma unroll
            for (int nt = 0; nt < 4; ++nt) {
                int n = wn * 32 + nt * 8 + (lane & 3) * 2;
                float bia0 = sB1[n], bia1 = sB1[n + 1];
                float w20  = sW2[n], w21  = sW2[n + 1];
                p0 = fmaf(fmaxf(acc[mf][nt][0] + bia0, 0.f), w20, p0);
                p0 = fmaf(fmaxf(acc[mf][nt][1] + bia1, 0.f), w21, p0);
                p1 = fmaf(fmaxf(acc[mf][nt][2] + bia0, 0.f), w20, p1);
                p1 = fmaf(fmaxf(acc[mf][nt][3] + bia1, 0.f), w21, p1);
            }
            p0 += __shfl_xor_sync(0xffffffffu, p0, 1);
            p0 += __shfl_xor_sync(0xffffffffu, p0, 2);
            p1 += __shfl_xor_sync(0xffffffffu, p1, 1);
            p1 += __shfl_xor_sync(0xffffffffu, p1, 2);
            if ((lane & 3) == 0) {
                int rr = wm * 32 + mf * 16 + (lane >> 2);
                sRed[rr * 4 + wn] = p0;
                sRed[(rr + 8) * 4 + wn] = p1;
            }
        }
        __syncthreads();   // next-buffer gather + sRed complete

        if (tid < TILE_E) {
            int e = e_base + tid;
            if (e < total) {
                float s = sRed[tid * 4] + sRed[tid * 4 + 1]
                        + sRed[tid * 4 + 2] + sRed[tid * 4 + 3] + b2v;
                out[e] = 1.f / (1.f + expf(-s));
            }
        }
        __syncthreads();   // out-reads of sRed done before next epilogue
    }
    #undef LOAD_IDX
    #undef FETCH_ROW
}

// ---------------------------------------------------------------------------
extern "C" void kernel_launch(void* const* d_in, const int* in_sizes, int n_in,
                              void* d_out, int out_size)
{
    const float* x  = (const float*)d_in[0];
    const float* W1 = (const float*)d_in[1];
    const float* b1 = (const float*)d_in[2];
    const float* W2 = (const float*)d_in[3];
    const float* b2 = (const float*)d_in[4];
    const int* eip  = (const int*)d_in[5];
    const int* ein  = (const int*)d_in[6];
    float* out = (float*)d_out;

    int E       = in_sizes[5] / 2;
    int total   = out_size;
    int n_tiles = (total + TILE_E - 1) / TILE_E;

    prep_kernel<<<16, 256>>>(W1);

    cudaFuncSetAttribute(vgae_mma_kernel,
                         cudaFuncAttributeMaxDynamicSharedMemorySize, SMEM_TOTAL);
    int grid = 148;
    if (grid > n_tiles) grid = n_tiles;
    vgae_mma_kernel<<<grid, NTHREADS, SMEM_TOTAL>>>(x, b1, W2, b2, eip, ein,
                                                    out, E, total, n_tiles);
}

// round 8
// speedup vs baseline: 5.4611x; 1.2476x over previous
#include <cuda_runtime.h>
#include <cuda_fp16.h>
#include <math.h>
#include <stdint.h>

typedef unsigned int u32;
typedef unsigned long long u64;

// ---------------------------------------------------------------------------
// vgae_decoder, warp-specialized fp16 mma (2-term A split):
//   D = Ahi@B + Alo@B,  B = fp16(W1)
// 148 persistent blocks x 512 threads, 128-edge tiles, double-buffered A.
//   warps 0-7  : producers (gather x rows, relu*mul, fp16 hi/lo split, STS)
//   warps 8-15 : consumers (MMA warp tile 32x64 = 4 m-strips x 2 n-strips,
//                fused epilogue: +b1, relu, dot W2, +b2, sigmoid, STG)
// One CTA barrier per iteration swaps buffers.
// ---------------------------------------------------------------------------

#define A_PITCH 272
#define SM_B   0
#define SM_A   32768
#define A_HALF 34816
#define A_BUF  (2 * A_HALF)              // 69632
#define SM_MISC (SM_A + 2 * A_BUF)       // 172032
#define SMEM_TOTAL (SM_MISC + 3072)
#define NTHREADS 512
#define TILE_E 128

__device__ u64 g_Bh[4096];   // fp16 W1 fragments, mma order

__device__ __forceinline__ u32 pack_hf2(__half a, __half b) {
    __half2 t; t.x = a; t.y = b; return *(u32*)&t;
}
__device__ __forceinline__ u32 smem_u32(const void* p) {
    u32 a; asm("{ .reg .u64 t; cvta.to.shared.u64 t, %1; cvt.u32.u64 %0, t; }"
               : "=r"(a) : "l"(p)); return a;
}
__device__ __forceinline__ void ldmatrix_x4(u32* r, u32 saddr) {
    asm volatile("ldmatrix.sync.aligned.m8n8.x4.shared.b16 {%0,%1,%2,%3}, [%4];"
                 : "=r"(r[0]), "=r"(r[1]), "=r"(r[2]), "=r"(r[3]) : "r"(saddr));
}
__device__ __forceinline__ void mma_fp16(float* d, const u32* a, const u32* b) {
    asm volatile(
        "mma.sync.aligned.m16n8k16.row.col.f32.f16.f16.f32 "
        "{%0,%1,%2,%3}, {%4,%5,%6,%7}, {%8,%9}, {%0,%1,%2,%3};"
        : "+f"(d[0]), "+f"(d[1]), "+f"(d[2]), "+f"(d[3])
        : "r"(a[0]), "r"(a[1]), "r"(a[2]), "r"(a[3]), "r"(b[0]), "r"(b[1]));
}

__global__ void prep_kernel(const float* __restrict__ W1) {
    int t = blockIdx.x * blockDim.x + threadIdx.x;
    if (t >= 4096) return;
    int lane = t & 31, nt = (t >> 5) & 15, kt = t >> 9;
    int n  = nt * 8 + (lane >> 2);
    int k0 = kt * 16 + (lane & 3) * 2;
    __half h0 = __float2half(W1[(k0    ) * 128 + n]);
    __half h1 = __float2half(W1[(k0 + 1) * 128 + n]);
    __half h2 = __float2half(W1[(k0 + 8) * 128 + n]);
    __half h3 = __float2half(W1[(k0 + 9) * 128 + n]);
    int idx = ((kt * 8 + (nt >> 1)) * 32 + lane) * 2 + (nt & 1);
    g_Bh[idx] = ((u64)pack_hf2(h2, h3) << 32) | pack_hf2(h0, h1);
}

__device__ __forceinline__ void conv_store(char* smem, u32 hi_base, int row,
                                           int lane, float4 a, float4 b,
                                           bool valid) {
    u64 hp = 0, lp = 0;
    if (valid) {
        float h0 = fmaxf(a.x * b.x, 0.f), h1 = fmaxf(a.y * b.y, 0.f);
        float h2 = fmaxf(a.z * b.z, 0.f), h3 = fmaxf(a.w * b.w, 0.f);
        __half e0 = __float2half(h0), e1 = __float2half(h1);
        __half e2 = __float2half(h2), e3 = __float2half(h3);
        u32 hi01 = pack_hf2(e0, e1), hi23 = pack_hf2(e2, e3);
        u32 lo01 = pack_hf2(__float2half(h0 - __half2float(e0)),
                            __float2half(h1 - __half2float(e1)));
        u32 lo23 = pack_hf2(__float2half(h2 - __half2float(e2)),
                            __float2half(h3 - __half2float(e3)));
        hp = ((u64)hi23 << 32) | hi01;
        lp = ((u64)lo23 << 32) | lo01;
    }
    u32 off = (u32)row * A_PITCH + (u32)lane * 8;
    *(u64*)(smem + hi_base + off)          = hp;
    *(u64*)(smem + hi_base + A_HALF + off) = lp;
}

__global__ void __launch_bounds__(NTHREADS, 1)
vgae_mma_kernel(const float* __restrict__ x,
                const float* __restrict__ b1g,
                const float* __restrict__ W2,
                const float* __restrict__ b2g,
                const int*   __restrict__ ei_pos,
                const int*   __restrict__ ei_neg,
                float*       __restrict__ out,
                int E, int total, int n_tiles)
{
    extern __shared__ char smem[];
    float* sB1  = (float*)(smem + SM_MISC);
    float* sW2  = (float*)(smem + SM_MISC + 512);
    float* sRed = (float*)(smem + SM_MISC + 1024);   // 128 x 2

    const int tid  = threadIdx.x;
    const int wid  = tid >> 5;
    const int lane = tid & 31;
    const u32 sbase = smem_u32(smem);

    {
        u64* bh = (u64*)(smem + SM_B);
        #pragma unroll 4
        for (int i = tid; i < 4096; i += NTHREADS) bh[i] = g_Bh[i];
        if (tid < 128) { sB1[tid] = b1g[tid]; sW2[tid] = W2[tid]; }
    }
    const float b2v = __ldg(b2g);

    const bool is_prod = (wid < 8);

    // ---- producer constants ----
    const int r0 = (wid & 7) * 16;   // producer rows r0..r0+15

    // index load for a tile: lanes 0-15 -> u of rows 0-15, lanes 16-31 -> v
    #define LOAD_IDX(T, IDXV) do {                                           \
        (IDXV) = 0;                                                          \
        int _e0 = (T) * TILE_E + r0;                                         \
        const int* _ei = ei_pos; int _el = _e0;                              \
        if (_el >= E) { _ei = ei_neg; _el -= E; }                            \
        if (_e0 + (lane & 15) < total)                                       \
            (IDXV) = __ldg(_ei + _el + (lane & 15) + ((lane >= 16) ? E : 0));\
    } while (0)

    #define FETCH_ROW(IDXV, J, A4, B4, VAL, TBASE) do {                      \
        (VAL) = ((TBASE) + r0 + (J)) < total;                                \
        int _u = __shfl_sync(0xffffffffu, (IDXV), (J));                      \
        int _v = __shfl_sync(0xffffffffu, (IDXV), (J) + 16);                 \
        (A4) = ((const float4*)(x + (size_t)_u * 128))[lane];                \
        (B4) = ((const float4*)(x + (size_t)_v * 128))[lane];                \
    } while (0)

    // gather 16 rows (2 waves of 8) of tile with base TBASE into buffer BASE
    #define GATHER16(IDXV, BASE, TBASE) do {                                 \
        _Pragma("unroll")                                                    \
        for (int w = 0; w < 2; ++w) {                                        \
            float4 xa[8], xb[8]; bool vv[8];                                 \
            _Pragma("unroll")                                                \
            for (int j = 0; j < 8; ++j)                                      \
                FETCH_ROW(IDXV, w * 8 + j, xa[j], xb[j], vv[j], TBASE);      \
            _Pragma("unroll")                                                \
            for (int j = 0; j < 8; ++j)                                      \
                conv_store(smem, BASE, r0 + w * 8 + j, lane, xa[j], xb[j],   \
                           vv[j]);                                           \
        }                                                                    \
    } while (0)

    // ---- consumer constants ----
    const int cw = wid - 8;          // 0..7
    const int wm = cw & 3;           // 32-row m-strip
    const int wn = cw >> 2;          // 64-col n-strip
    const u32 a_lm0 = (u32)(wm * 32 + (lane & 15)) * A_PITCH
                    + (u32)(lane >> 4) * 16;
    const int ct = tid - 256;        // consumer thread index 0..255

    // ---- prologue: producers gather tile0 into buffer 0 ----
    if (is_prod) {
        int tile0 = blockIdx.x;
        int idxv; LOAD_IDX(tile0, idxv);
        GATHER16(idxv, SM_A, tile0 * TILE_E);
    }
    __syncthreads();

    int idx_pf = 0;
    if (is_prod && blockIdx.x + gridDim.x < n_tiles)
        LOAD_IDX(blockIdx.x + gridDim.x, idx_pf);

    int it = 0;
    for (int tile = blockIdx.x; tile < n_tiles; tile += gridDim.x, ++it) {
        const int cur = it & 1;

        if (is_prod) {
            // ======== producer: gather tile+grid into buffer cur^1 ========
            const int tnx = tile + gridDim.x;
            if (tnx < n_tiles) {
                int idxv = idx_pf;
                if (tnx + gridDim.x < n_tiles)
                    LOAD_IDX(tnx + gridDim.x, idx_pf);   // prefetch next idx
                GATHER16(idxv, SM_A + (u32)(cur ^ 1) * A_BUF, tnx * TILE_E);
            }
        } else {
            // ======== consumer: MMA on buffer cur + fused epilogue ========
            const u32 a_lm = sbase + SM_A + (u32)cur * A_BUF + a_lm0;

            float acc[2][8][4];
            #pragma unroll
            for (int mf = 0; mf < 2; ++mf)
                #pragma unroll
                for (int nt = 0; nt < 8; ++nt)
                    #pragma unroll
                    for (int c = 0; c < 4; ++c) acc[mf][nt][c] = 0.f;

            #pragma unroll
            for (int kt = 0; kt < 8; ++kt) {
                u32 ah[2][4], al[2][4];
                #pragma unroll
                for (int mf = 0; mf < 2; ++mf) {
                    u32 ad = a_lm + (u32)mf * (16 * A_PITCH) + (u32)kt * 32;
                    ldmatrix_x4(ah[mf], ad);
                    ldmatrix_x4(al[mf], ad + A_HALF);
                }
                u32 bq[8][2];
                #pragma unroll
                for (int np = 0; np < 4; ++np) {
                    u32 boff = (u32)(((kt * 8 + wn * 4 + np) * 32 + lane)
                                     * 16);
                    uint4 q = *(const uint4*)(smem + SM_B + boff);
                    bq[np*2][0] = q.x; bq[np*2][1] = q.y;
                    bq[np*2+1][0] = q.z; bq[np*2+1][1] = q.w;
                }
                #pragma unroll
                for (int mf = 0; mf < 2; ++mf)
                    #pragma unroll
                    for (int nt = 0; nt < 8; ++nt) {
                        mma_fp16(acc[mf][nt], ah[mf], bq[nt]);
                        mma_fp16(acc[mf][nt], al[mf], bq[nt]);
                    }
            }

            // epilogue: +b1, relu, dot W2, shfl-reduce, stash partials
            #pragma unroll
            for (int mf = 0; mf < 2; ++mf) {
                float p0 = 0.f, p1 = 0.f;
                #pragma unroll
                for (int nt = 0; nt < 8; ++nt) {
                    int n = wn * 64 + nt * 8 + (lane & 3) * 2;
                    float bia0 = sB1[n], bia1 = sB1[n + 1];
                    float w20  = sW2[n], w21  = sW2[n + 1];
                    p0 = fmaf(fmaxf(acc[mf][nt][0] + bia0, 0.f), w20, p0);
                    p0 = fmaf(fmaxf(acc[mf][nt][1] + bia1, 0.f), w21, p0);
                    p1 = fmaf(fmaxf(acc[mf][nt][2] + bia0, 0.f), w20, p1);
                    p1 = fmaf(fmaxf(acc[mf][nt][3] + bia1, 0.f), w21, p1);
                }
                p0 += __shfl_xor_sync(0xffffffffu, p0, 1);
                p0 += __shfl_xor_sync(0xffffffffu, p0, 2);
                p1 += __shfl_xor_sync(0xffffffffu, p1, 1);
                p1 += __shfl_xor_sync(0xffffffffu, p1, 2);
                if ((lane & 3) == 0) {
                    int rr = wm * 32 + mf * 16 + (lane >> 2);
                    sRed[rr * 2 + wn] = p0;
                    sRed[(rr + 8) * 2 + wn] = p1;
                }
            }
            // consumer-group barrier (named, 256 threads)
            asm volatile("bar.sync 1, 256;" ::: "memory");

            if (ct < TILE_E) {
                int e = tile * TILE_E + ct;
                if (e < total) {
                    float s = sRed[ct * 2] + sRed[ct * 2 + 1] + b2v;
                    out[e] = 1.f / (1.f + expf(-s));
                }
            }
        }

        __syncthreads();   // swap buffers: gather(cur^1) done, MMA(cur) done
    }
    #undef LOAD_IDX
    #undef FETCH_ROW
    #undef GATHER16
}

// ---------------------------------------------------------------------------
extern "C" void kernel_launch(void* const* d_in, const int* in_sizes, int n_in,
                              void* d_out, int out_size)
{
    const float* x  = (const float*)d_in[0];
    const float* W1 = (const float*)d_in[1];
    const float* b1 = (const float*)d_in[2];
    const float* W2 = (const float*)d_in[3];
    const float* b2 = (const float*)d_in[4];
    const int* eip  = (const int*)d_in[5];
    const int* ein  = (const int*)d_in[6];
    float* out = (float*)d_out;

    int E       = in_sizes[5] / 2;
    int total   = out_size;
    int n_tiles = (total + TILE_E - 1) / TILE_E;

    prep_kernel<<<16, 256>>>(W1);

    cudaFuncSetAttribute(vgae_mma_kernel,
                         cudaFuncAttributeMaxDynamicSharedMemorySize, SMEM_TOTAL);
    int grid = 148;
    if (grid > n_tiles) grid = n_tiles;
    vgae_mma_kernel<<<grid, NTHREADS, SMEM_TOTAL>>>(x, b1, W2, b2, eip, ein,
                                                    out, E, total, n_tiles);
}

// round 9
// speedup vs baseline: 7.6240x; 1.3961x over previous
#include <cuda_runtime.h>
#include <cuda_fp16.h>
#include <math.h>
#include <stdint.h>

typedef unsigned int u32;
typedef unsigned long long u64;

// ---------------------------------------------------------------------------
// vgae_decoder, warp-specialized single-pass fp16 mma:
//   D = fp16(relu(x_u*x_v)) @ fp16(W1)   (fp32 accumulate)
// Error budget: ~1e-4 rel (gate 1e-3).
// 148 persistent blocks x 512 threads, 128-edge tiles, double-buffered A.
//   warps 0-7  : producers (gather x rows, relu*mul, fp16, STS)
//   warps 8-15 : consumers (MMA warp tile 32x64, fused epilogue)
// ---------------------------------------------------------------------------

#define A_PITCH 272
#define SM_B   0
#define SM_A   32768
#define A_BUF  34816                     // one fp16 plane (128*272)
#define SM_MISC (SM_A + 2 * A_BUF)       // 102400
#define SMEM_TOTAL (SM_MISC + 3072)      // 105472
#define NTHREADS 512
#define TILE_E 128

__device__ u64 g_Bh[4096];   // fp16 W1 fragments, mma order

__device__ __forceinline__ u32 pack_hf2(__half a, __half b) {
    __half2 t; t.x = a; t.y = b; return *(u32*)&t;
}
__device__ __forceinline__ u32 smem_u32(const void* p) {
    u32 a; asm("{ .reg .u64 t; cvta.to.shared.u64 t, %1; cvt.u32.u64 %0, t; }"
               : "=r"(a) : "l"(p)); return a;
}
__device__ __forceinline__ void ldmatrix_x4(u32* r, u32 saddr) {
    asm volatile("ldmatrix.sync.aligned.m8n8.x4.shared.b16 {%0,%1,%2,%3}, [%4];"
                 : "=r"(r[0]), "=r"(r[1]), "=r"(r[2]), "=r"(r[3]) : "r"(saddr));
}
__device__ __forceinline__ void mma_fp16(float* d, const u32* a, const u32* b) {
    asm volatile(
        "mma.sync.aligned.m16n8k16.row.col.f32.f16.f16.f32 "
        "{%0,%1,%2,%3}, {%4,%5,%6,%7}, {%8,%9}, {%0,%1,%2,%3};"
        : "+f"(d[0]), "+f"(d[1]), "+f"(d[2]), "+f"(d[3])
        : "r"(a[0]), "r"(a[1]), "r"(a[2]), "r"(a[3]), "r"(b[0]), "r"(b[1]));
}

__global__ void prep_kernel(const float* __restrict__ W1) {
    int t = blockIdx.x * blockDim.x + threadIdx.x;
    if (t >= 4096) return;
    int lane = t & 31, nt = (t >> 5) & 15, kt = t >> 9;
    int n  = nt * 8 + (lane >> 2);
    int k0 = kt * 16 + (lane & 3) * 2;
    __half h0 = __float2half(W1[(k0    ) * 128 + n]);
    __half h1 = __float2half(W1[(k0 + 1) * 128 + n]);
    __half h2 = __float2half(W1[(k0 + 8) * 128 + n]);
    __half h3 = __float2half(W1[(k0 + 9) * 128 + n]);
    int idx = ((kt * 8 + (nt >> 1)) * 32 + lane) * 2 + (nt & 1);
    g_Bh[idx] = ((u64)pack_hf2(h2, h3) << 32) | pack_hf2(h0, h1);
}

__device__ __forceinline__ void conv_store(char* smem, u32 base, int row,
                                           int lane, float4 a, float4 b,
                                           bool valid) {
    u64 hp = 0;
    if (valid) {
        float h0 = fmaxf(a.x * b.x, 0.f), h1 = fmaxf(a.y * b.y, 0.f);
        float h2 = fmaxf(a.z * b.z, 0.f), h3 = fmaxf(a.w * b.w, 0.f);
        u32 hi01 = pack_hf2(__float2half(h0), __float2half(h1));
        u32 hi23 = pack_hf2(__float2half(h2), __float2half(h3));
        hp = ((u64)hi23 << 32) | hi01;
    }
    u32 off = (u32)row * A_PITCH + (u32)lane * 8;
    *(u64*)(smem + base + off) = hp;
}

__global__ void __launch_bounds__(NTHREADS, 1)
vgae_mma_kernel(const float* __restrict__ x,
                const float* __restrict__ b1g,
                const float* __restrict__ W2,
                const float* __restrict__ b2g,
                const int*   __restrict__ ei_pos,
                const int*   __restrict__ ei_neg,
                float*       __restrict__ out,
                int E, int total, int n_tiles)
{
    extern __shared__ char smem[];
    float* sB1  = (float*)(smem + SM_MISC);
    float* sW2  = (float*)(smem + SM_MISC + 512);
    float* sRed = (float*)(smem + SM_MISC + 1024);   // 128 x 2

    const int tid  = threadIdx.x;
    const int wid  = tid >> 5;
    const int lane = tid & 31;
    const u32 sbase = smem_u32(smem);

    {
        u64* bh = (u64*)(smem + SM_B);
        #pragma unroll 4
        for (int i = tid; i < 4096; i += NTHREADS) bh[i] = g_Bh[i];
        if (tid < 128) { sB1[tid] = b1g[tid]; sW2[tid] = W2[tid]; }
    }
    const float b2v = __ldg(b2g);

    const bool is_prod = (wid < 8);
    const int r0 = (wid & 7) * 16;   // producer rows r0..r0+15

    #define LOAD_IDX(T, IDXV) do {                                           \
        (IDXV) = 0;                                                          \
        int _e0 = (T) * TILE_E + r0;                                         \
        const int* _ei = ei_pos; int _el = _e0;                              \
        if (_el >= E) { _ei = ei_neg; _el -= E; }                            \
        if (_e0 + (lane & 15) < total)                                       \
            (IDXV) = __ldg(_ei + _el + (lane & 15) + ((lane >= 16) ? E : 0));\
    } while (0)

    #define FETCH_ROW(IDXV, J, A4, B4, VAL, TBASE) do {                      \
        (VAL) = ((TBASE) + r0 + (J)) < total;                                \
        int _u = __shfl_sync(0xffffffffu, (IDXV), (J));                      \
        int _v = __shfl_sync(0xffffffffu, (IDXV), (J) + 16);                 \
        (A4) = ((const float4*)(x + (size_t)_u * 128))[lane];                \
        (B4) = ((const float4*)(x + (size_t)_v * 128))[lane];                \
    } while (0)

    #define GATHER16(IDXV, BASE, TBASE) do {                                 \
        _Pragma("unroll")                                                    \
        for (int w = 0; w < 2; ++w) {                                        \
            float4 xa[8], xb[8]; bool vv[8];                                 \
            _Pragma("unroll")                                                \
            for (int j = 0; j < 8; ++j)                                      \
                FETCH_ROW(IDXV, w * 8 + j, xa[j], xb[j], vv[j], TBASE);      \
            _Pragma("unroll")                                                \
            for (int j = 0; j < 8; ++j)                                      \
                conv_store(smem, BASE, r0 + w * 8 + j, lane, xa[j], xb[j],   \
                           vv[j]);                                           \
        }                                                                    \
    } while (0)

    // ---- consumer constants ----
    const int cw = wid - 8;
    const int wm = cw & 3;           // 32-row m-strip
    const int wn = cw >> 2;          // 64-col n-strip
    const u32 a_lm0 = (u32)(wm * 32 + (lane & 15)) * A_PITCH
                    + (u32)(lane >> 4) * 16;
    const int ct = tid - 256;

    // ---- prologue ----
    if (is_prod) {
        int tile0 = blockIdx.x;
        int idxv; LOAD_IDX(tile0, idxv);
        GATHER16(idxv, SM_A, tile0 * TILE_E);
    }
    __syncthreads();

    int idx_pf = 0;
    if (is_prod && blockIdx.x + gridDim.x < n_tiles)
        LOAD_IDX(blockIdx.x + gridDim.x, idx_pf);

    int it = 0;
    for (int tile = blockIdx.x; tile < n_tiles; tile += gridDim.x, ++it) {
        const int cur = it & 1;

        if (is_prod) {
            const int tnx = tile + gridDim.x;
            if (tnx < n_tiles) {
                int idxv = idx_pf;
                if (tnx + gridDim.x < n_tiles)
                    LOAD_IDX(tnx + gridDim.x, idx_pf);
                GATHER16(idxv, SM_A + (u32)(cur ^ 1) * A_BUF, tnx * TILE_E);
            }
        } else {
            const u32 a_lm = sbase + SM_A + (u32)cur * A_BUF + a_lm0;

            float acc[2][8][4];
            #pragma unroll
            for (int mf = 0; mf < 2; ++mf)
                #pragma unroll
                for (int nt = 0; nt < 8; ++nt)
                    #pragma unroll
                    for (int c = 0; c < 4; ++c) acc[mf][nt][c] = 0.f;

            #pragma unroll
            for (int kt = 0; kt < 8; ++kt) {
                u32 ah[2][4];
                #pragma unroll
                for (int mf = 0; mf < 2; ++mf)
                    ldmatrix_x4(ah[mf],
                                a_lm + (u32)mf * (16 * A_PITCH) + (u32)kt * 32);
                u32 bq[8][2];
                #pragma unroll
                for (int np = 0; np < 4; ++np) {
                    u32 boff = (u32)(((kt * 8 + wn * 4 + np) * 32 + lane)
                                     * 16);
                    uint4 q = *(const uint4*)(smem + SM_B + boff);
                    bq[np*2][0] = q.x; bq[np*2][1] = q.y;
                    bq[np*2+1][0] = q.z; bq[np*2+1][1] = q.w;
                }
                #pragma unroll
                for (int mf = 0; mf < 2; ++mf)
                    #pragma unroll
                    for (int nt = 0; nt < 8; ++nt)
                        mma_fp16(acc[mf][nt], ah[mf], bq[nt]);
            }

            #pragma unroll
            for (int mf = 0; mf < 2; ++mf) {
                float p0 = 0.f, p1 = 0.f;
                #pragma unroll
                for (int nt = 0; nt < 8; ++nt) {
                    int n = wn * 64 + nt * 8 + (lane & 3) * 2;
                    float bia0 = sB1[n], bia1 = sB1[n + 1];
                    float w20  = sW2[n], w21  = sW2[n + 1];
                    p0 = fmaf(fmaxf(acc[mf][nt][0] + bia0, 0.f), w20, p0);
                    p0 = fmaf(fmaxf(acc[mf][nt][1] + bia1, 0.f), w21, p0);
                    p1 = fmaf(fmaxf(acc[mf][nt][2] + bia0, 0.f), w20, p1);
                    p1 = fmaf(fmaxf(acc[mf][nt][3] + bia1, 0.f), w21, p1);
                }
                p0 += __shfl_xor_sync(0xffffffffu, p0, 1);
                p0 += __shfl_xor_sync(0xffffffffu, p0, 2);
                p1 += __shfl_xor_sync(0xffffffffu, p1, 1);
                p1 += __shfl_xor_sync(0xffffffffu, p1, 2);
                if ((lane & 3) == 0) {
                    int rr = wm * 32 + mf * 16 + (lane >> 2);
                    sRed[rr * 2 + wn] = p0;
                    sRed[(rr + 8) * 2 + wn] = p1;
                }
            }
            asm volatile("bar.sync 1, 256;" ::: "memory");

            if (ct < TILE_E) {
                int e = tile * TILE_E + ct;
                if (e < total) {
                    float s = sRed[ct * 2] + sRed[ct * 2 + 1] + b2v;
                    out[e] = 1.f / (1.f + expf(-s));
                }
            }
        }

        __syncthreads();
    }
    #undef LOAD_IDX
    #undef FETCH_ROW
    #undef GATHER16
}

// ---------------------------------------------------------------------------
extern "C" void kernel_launch(void* const* d_in, const int* in_sizes, int n_in,
                              void* d_out, int out_size)
{
    const float* x  = (const float*)d_in[0];
    const float* W1 = (const float*)d_in[1];
    const float* b1 = (const float*)d_in[2];
    const float* W2 = (const float*)d_in[3];
    const float* b2 = (const float*)d_in[4];
    const int* eip  = (const int*)d_in[5];
    const int* ein  = (const int*)d_in[6];
    float* out = (float*)d_out;

    int E       = in_sizes[5] / 2;
    int total   = out_size;
    int n_tiles = (total + TILE_E - 1) / TILE_E;

    prep_kernel<<<16, 256>>>(W1);

    cudaFuncSetAttribute(vgae_mma_kernel,
                         cudaFuncAttributeMaxDynamicSharedMemorySize, SMEM_TOTAL);
    int grid = 148;
    if (grid > n_tiles) grid = n_tiles;
    vgae_mma_kernel<<<grid, NTHREADS, SMEM_TOTAL>>>(x, b1, W2, b2, eip, ein,
                                                    out, E, total, n_tiles);
}

// round 10
// speedup vs baseline: 7.7788x; 1.0203x over previous
#include <cuda_runtime.h>
#include <cuda_fp16.h>
#include <math.h>
#include <stdint.h>

typedef unsigned int u32;
typedef unsigned long long u64;

// ---------------------------------------------------------------------------
// vgae_decoder, warp-specialized single-pass fp16 mma:
//   D = fp16(relu(x_u*x_v)) @ fp16(W1)   (fp32 accumulate)
// R10: x gathers via ld.global.nc.L1::no_allocate (no L1 fill traffic);
//      epilogue STG deferred to producer warps (double-buffered sRed).
// 148 persistent blocks x 512 threads, 128-edge tiles, double-buffered A.
// ---------------------------------------------------------------------------

#define A_PITCH 272
#define SM_B   0
#define SM_A   32768
#define A_BUF  34816                     // one fp16 plane (128*272)
#define SM_MISC (SM_A + 2 * A_BUF)       // 102400
#define SMEM_TOTAL (SM_MISC + 4096)      // 106496
#define NTHREADS 512
#define TILE_E 128

__device__ u64 g_Bh[4096];   // fp16 W1 fragments, mma order

__device__ __forceinline__ u32 pack_hf2(__half a, __half b) {
    __half2 t; t.x = a; t.y = b; return *(u32*)&t;
}
__device__ __forceinline__ u32 smem_u32(const void* p) {
    u32 a; asm("{ .reg .u64 t; cvta.to.shared.u64 t, %1; cvt.u32.u64 %0, t; }"
               : "=r"(a) : "l"(p)); return a;
}
__device__ __forceinline__ void ldmatrix_x4(u32* r, u32 saddr) {
    asm volatile("ldmatrix.sync.aligned.m8n8.x4.shared.b16 {%0,%1,%2,%3}, [%4];"
                 : "=r"(r[0]), "=r"(r[1]), "=r"(r[2]), "=r"(r[3]) : "r"(saddr));
}
__device__ __forceinline__ void mma_fp16(float* d, const u32* a, const u32* b) {
    asm volatile(
        "mma.sync.aligned.m16n8k16.row.col.f32.f16.f16.f32 "
        "{%0,%1,%2,%3}, {%4,%5,%6,%7}, {%8,%9}, {%0,%1,%2,%3};"
        : "+f"(d[0]), "+f"(d[1]), "+f"(d[2]), "+f"(d[3])
        : "r"(a[0]), "r"(a[1]), "r"(a[2]), "r"(a[3]), "r"(b[0]), "r"(b[1]));
}
// x-row load: bypass L1 allocation (x has ~0% L1 reuse; reuse lives in L2)
__device__ __forceinline__ float4 ldg_na(const float* p) {
    float4 v;
    asm volatile("ld.global.nc.L1::no_allocate.v4.f32 {%0,%1,%2,%3}, [%4];"
                 : "=f"(v.x), "=f"(v.y), "=f"(v.z), "=f"(v.w) : "l"(p));
    return v;
}

__global__ void prep_kernel(const float* __restrict__ W1) {
    int t = blockIdx.x * blockDim.x + threadIdx.x;
    if (t >= 4096) return;
    int lane = t & 31, nt = (t >> 5) & 15, kt = t >> 9;
    int n  = nt * 8 + (lane >> 2);
    int k0 = kt * 16 + (lane & 3) * 2;
    __half h0 = __float2half(W1[(k0    ) * 128 + n]);
    __half h1 = __float2half(W1[(k0 + 1) * 128 + n]);
    __half h2 = __float2half(W1[(k0 + 8) * 128 + n]);
    __half h3 = __float2half(W1[(k0 + 9) * 128 + n]);
    int idx = ((kt * 8 + (nt >> 1)) * 32 + lane) * 2 + (nt & 1);
    g_Bh[idx] = ((u64)pack_hf2(h2, h3) << 32) | pack_hf2(h0, h1);
}

__device__ __forceinline__ void conv_store(char* smem, u32 base, int row,
                                           int lane, float4 a, float4 b,
                                           bool valid) {
    u64 hp = 0;
    if (valid) {
        float h0 = fmaxf(a.x * b.x, 0.f), h1 = fmaxf(a.y * b.y, 0.f);
        float h2 = fmaxf(a.z * b.z, 0.f), h3 = fmaxf(a.w * b.w, 0.f);
        u32 hi01 = pack_hf2(__float2half(h0), __float2half(h1));
        u32 hi23 = pack_hf2(__float2half(h2), __float2half(h3));
        hp = ((u64)hi23 << 32) | hi01;
    }
    u32 off = (u32)row * A_PITCH + (u32)lane * 8;
    *(u64*)(smem + base + off) = hp;
}

__global__ void __launch_bounds__(NTHREADS, 1)
vgae_mma_kernel(const float* __restrict__ x,
                const float* __restrict__ b1g,
                const float* __restrict__ W2,
                const float* __restrict__ b2g,
                const int*   __restrict__ ei_pos,
                const int*   __restrict__ ei_neg,
                float*       __restrict__ out,
                int E, int total, int n_tiles)
{
    extern __shared__ char smem[];
    float* sB1  = (float*)(smem + SM_MISC);
    float* sW2  = (float*)(smem + SM_MISC + 512);
    float* sRed = (float*)(smem + SM_MISC + 1024);   // [2][128][2] f32

    const int tid  = threadIdx.x;
    const int wid  = tid >> 5;
    const int lane = tid & 31;
    const u32 sbase = smem_u32(smem);

    {
        u64* bh = (u64*)(smem + SM_B);
        #pragma unroll 4
        for (int i = tid; i < 4096; i += NTHREADS) bh[i] = g_Bh[i];
        if (tid < 128) { sB1[tid] = b1g[tid]; sW2[tid] = W2[tid]; }
    }
    const float b2v = __ldg(b2g);

    const bool is_prod = (wid < 8);
    const int r0 = (wid & 7) * 16;   // producer rows r0..r0+15

    #define LOAD_IDX(T, IDXV) do {                                           \
        (IDXV) = 0;                                                          \
        int _e0 = (T) * TILE_E + r0;                                         \
        const int* _ei = ei_pos; int _el = _e0;                              \
        if (_el >= E) { _ei = ei_neg; _el -= E; }                            \
        if (_e0 + (lane & 15) < total)                                       \
            (IDXV) = __ldg(_ei + _el + (lane & 15) + ((lane >= 16) ? E : 0));\
    } while (0)

    #define FETCH_ROW(IDXV, J, A4, B4, VAL, TBASE) do {                      \
        (VAL) = ((TBASE) + r0 + (J)) < total;                                \
        int _u = __shfl_sync(0xffffffffu, (IDXV), (J));                      \
        int _v = __shfl_sync(0xffffffffu, (IDXV), (J) + 16);                 \
        (A4) = ldg_na(x + (size_t)_u * 128 + lane * 4);                      \
        (B4) = ldg_na(x + (size_t)_v * 128 + lane * 4);                      \
    } while (0)

    #define GATHER16(IDXV, BASE, TBASE) do {                                 \
        _Pragma("unroll")                                                    \
        for (int w = 0; w < 2; ++w) {                                        \
            float4 xa[8], xb[8]; bool vv[8];                                 \
            _Pragma("unroll")                                                \
            for (int j = 0; j < 8; ++j)                                      \
                FETCH_ROW(IDXV, w * 8 + j, xa[j], xb[j], vv[j], TBASE);      \
            _Pragma("unroll")                                                \
            for (int j = 0; j < 8; ++j)                                      \
                conv_store(smem, BASE, r0 + w * 8 + j, lane, xa[j], xb[j],   \
                           vv[j]);                                           \
        }                                                                    \
    } while (0)

    // ---- consumer constants ----
    const int cw = wid - 8;
    const int wm = cw & 3;           // 32-row m-strip
    const int wn = cw >> 2;          // 64-col n-strip
    const u32 a_lm0 = (u32)(wm * 32 + (lane & 15)) * A_PITCH
                    + (u32)(lane >> 4) * 16;

    // ---- prologue ----
    if (is_prod) {
        int tile0 = blockIdx.x;
        int idxv; LOAD_IDX(tile0, idxv);
        GATHER16(idxv, SM_A, tile0 * TILE_E);
    }
    __syncthreads();

    int idx_pf = 0;
    if (is_prod && blockIdx.x + gridDim.x < n_tiles)
        LOAD_IDX(blockIdx.x + gridDim.x, idx_pf);

    const int nit = (n_tiles - blockIdx.x + gridDim.x - 1) / gridDim.x;

    int it = 0;
    for (int tile = blockIdx.x; tile < n_tiles; tile += gridDim.x, ++it) {
        const int cur = it & 1;

        if (is_prod) {
            // -- deferred epilogue STG for previous tile (overlaps MMA) --
            if (it > 0 && tid < TILE_E) {
                int e = (tile - gridDim.x) * TILE_E + tid;
                if (e < total) {
                    const float* rp = sRed + (cur ^ 1) * 256 + tid * 2;
                    float s = rp[0] + rp[1] + b2v;
                    out[e] = 1.f / (1.f + expf(-s));
                }
            }
            // -- gather tile+grid into buffer cur^1 --
            const int tnx = tile + gridDim.x;
            if (tnx < n_tiles) {
                int idxv = idx_pf;
                if (tnx + gridDim.x < n_tiles)
                    LOAD_IDX(tnx + gridDim.x, idx_pf);
                GATHER16(idxv, SM_A + (u32)(cur ^ 1) * A_BUF, tnx * TILE_E);
            }
        } else {
            const u32 a_lm = sbase + SM_A + (u32)cur * A_BUF + a_lm0;

            float acc[2][8][4];
            #pragma unroll
            for (int mf = 0; mf < 2; ++mf)
                #pragma unroll
                for (int nt = 0; nt < 8; ++nt)
                    #pragma unroll
                    for (int c = 0; c < 4; ++c) acc[mf][nt][c] = 0.f;

            #pragma unroll
            for (int kt = 0; kt < 8; ++kt) {
                u32 ah[2][4];
                #pragma unroll
                for (int mf = 0; mf < 2; ++mf)
                    ldmatrix_x4(ah[mf],
                                a_lm + (u32)mf * (16 * A_PITCH) + (u32)kt * 32);
                u32 bq[8][2];
                #pragma unroll
                for (int np = 0; np < 4; ++np) {
                    u32 boff = (u32)(((kt * 8 + wn * 4 + np) * 32 + lane)
                                     * 16);
                    uint4 q = *(const uint4*)(smem + SM_B + boff);
                    bq[np*2][0] = q.x; bq[np*2][1] = q.y;
                    bq[np*2+1][0] = q.z; bq[np*2+1][1] = q.w;
                }
                #pragma unroll
                for (int mf = 0; mf < 2; ++mf)
                    #pragma unroll
                    for (int nt = 0; nt < 8; ++nt)
                        mma_fp16(acc[mf][nt], ah[mf], bq[nt]);
            }

            // partial epilogue: +b1, relu, dot W2, shfl-reduce -> sRed[cur]
            #pragma unroll
            for (int mf = 0; mf < 2; ++mf) {
                float p0 = 0.f, p1 = 0.f;
                #pragma unroll
                for (int nt = 0; nt < 8; ++nt) {
                    int n = wn * 64 + nt * 8 + (lane & 3) * 2;
                    float bia0 = sB1[n], bia1 = sB1[n + 1];
                    float w20  = sW2[n], w21  = sW2[n + 1];
                    p0 = fmaf(fmaxf(acc[mf][nt][0] + bia0, 0.f), w20, p0);
                    p0 = fmaf(fmaxf(acc[mf][nt][1] + bia1, 0.f), w21, p0);
                    p1 = fmaf(fmaxf(acc[mf][nt][2] + bia0, 0.f), w20, p1);
                    p1 = fmaf(fmaxf(acc[mf][nt][3] + bia1, 0.f), w21, p1);
                }
                p0 += __shfl_xor_sync(0xffffffffu, p0, 1);
                p0 += __shfl_xor_sync(0xffffffffu, p0, 2);
                p1 += __shfl_xor_sync(0xffffffffu, p1, 1);
                p1 += __shfl_xor_sync(0xffffffffu, p1, 2);
                if ((lane & 3) == 0) {
                    int rr = wm * 32 + mf * 16 + (lane >> 2);
                    float* rb = sRed + cur * 256;
                    rb[rr * 2 + wn] = p0;
                    rb[(rr + 8) * 2 + wn] = p1;
                }
            }
        }

        __syncthreads();   // A-buf swap + sRed[cur] visible to producers
    }

    // ---- drain: STG for the last tile ----
    if (tid < TILE_E) {
        int tile_last = blockIdx.x + (nit - 1) * gridDim.x;
        int e = tile_last * TILE_E + tid;
        if (e < total) {
            const float* rp = sRed + ((nit - 1) & 1) * 256 + tid * 2;
            float s = rp[0] + rp[1] + b2v;
            out[e] = 1.f / (1.f + expf(-s));
        }
    }
    #undef LOAD_IDX
    #undef FETCH_ROW
    #undef GATHER16
}

// ---------------------------------------------------------------------------
extern "C" void kernel_launch(void* const* d_in, const int* in_sizes, int n_in,
                              void* d_out, int out_size)
{
    const float* x  = (const float*)d_in[0];
    const float* W1 = (const float*)d_in[1];
    const float* b1 = (const float*)d_in[2];
    const float* W2 = (const float*)d_in[3];
    const float* b2 = (const float*)d_in[4];
    const int* eip  = (const int*)d_in[5];
    const int* ein  = (const int*)d_in[6];
    float* out = (float*)d_out;

    int E       = in_sizes[5] / 2;
    int total   = out_size;
    int n_tiles = (total + TILE_E - 1) / TILE_E;

    prep_kernel<<<16, 256>>>(W1);

    cudaFuncSetAttribute(vgae_mma_kernel,
                         cudaFuncAttributeMaxDynamicSharedMemorySize, SMEM_TOTAL);
    int grid = 148;
    if (grid > n_tiles) grid = n_tiles;
    vgae_mma_kernel<<<grid, NTHREADS, SMEM_TOTAL>>>(x, b1, W2, b2, eip, ein,
                                                    out, E, total, n_tiles);
}

// round 11
// speedup vs baseline: 8.0760x; 1.0382x over previous
#include <cuda_runtime.h>
#include <cuda_fp16.h>
#include <math.h>
#include <stdint.h>

typedef unsigned int u32;
typedef unsigned long long u64;

// ---------------------------------------------------------------------------
// vgae_decoder, warp-specialized single-pass fp16 mma:
//   D = fp16(relu(x_u*x_v)) @ fp16(W1)   (fp32 accumulate)
// R11: triple-buffered A ring + split named barriers (producers decoupled,
//      run up to 2 tiles ahead; no CTA-wide barrier in the loop).
//   warps 0-7  : producers (gather, convert, STS; deferred epilogue STG)
//   warps 8-15 : consumers (MMA 32x64 warp tile, partial epilogue -> sRed)
// Barriers: full[b] = id 1+b (prod arrive, cons sync), free[b] = id 4+b.
// ---------------------------------------------------------------------------

#define A_PITCH 272
#define SM_B   0
#define SM_A   32768
#define A_BUF  34816                     // one fp16 plane (128*272)
#define NBUF   3
#define SM_MISC (SM_A + NBUF * A_BUF)    // 137216
#define SMEM_TOTAL (SM_MISC + 4608)      // 141824
#define NTHREADS 512
#define TILE_E 128

__device__ u64 g_Bh[4096];   // fp16 W1 fragments, mma order

#define NB_ARRIVE(id) asm volatile("bar.arrive %0, 512;" :: "r"(id) : "memory")
#define NB_SYNC(id)   asm volatile("bar.sync %0, 512;"   :: "r"(id) : "memory")

__device__ __forceinline__ u32 pack_hf2(__half a, __half b) {
    __half2 t; t.x = a; t.y = b; return *(u32*)&t;
}
__device__ __forceinline__ u32 smem_u32(const void* p) {
    u32 a; asm("{ .reg .u64 t; cvta.to.shared.u64 t, %1; cvt.u32.u64 %0, t; }"
               : "=r"(a) : "l"(p)); return a;
}
__device__ __forceinline__ void ldmatrix_x4(u32* r, u32 saddr) {
    asm volatile("ldmatrix.sync.aligned.m8n8.x4.shared.b16 {%0,%1,%2,%3}, [%4];"
                 : "=r"(r[0]), "=r"(r[1]), "=r"(r[2]), "=r"(r[3]) : "r"(saddr));
}
__device__ __forceinline__ void mma_fp16(float* d, const u32* a, const u32* b) {
    asm volatile(
        "mma.sync.aligned.m16n8k16.row.col.f32.f16.f16.f32 "
        "{%0,%1,%2,%3}, {%4,%5,%6,%7}, {%8,%9}, {%0,%1,%2,%3};"
        : "+f"(d[0]), "+f"(d[1]), "+f"(d[2]), "+f"(d[3])
        : "r"(a[0]), "r"(a[1]), "r"(a[2]), "r"(a[3]), "r"(b[0]), "r"(b[1]));
}
__device__ __forceinline__ float4 ldg_na(const float* p) {
    float4 v;
    asm volatile("ld.global.nc.L1::no_allocate.v4.f32 {%0,%1,%2,%3}, [%4];"
                 : "=f"(v.x), "=f"(v.y), "=f"(v.z), "=f"(v.w) : "l"(p));
    return v;
}

__global__ void prep_kernel(const float* __restrict__ W1) {
    int t = blockIdx.x * blockDim.x + threadIdx.x;
    if (t >= 4096) return;
    int lane = t & 31, nt = (t >> 5) & 15, kt = t >> 9;
    int n  = nt * 8 + (lane >> 2);
    int k0 = kt * 16 + (lane & 3) * 2;
    __half h0 = __float2half(W1[(k0    ) * 128 + n]);
    __half h1 = __float2half(W1[(k0 + 1) * 128 + n]);
    __half h2 = __float2half(W1[(k0 + 8) * 128 + n]);
    __half h3 = __float2half(W1[(k0 + 9) * 128 + n]);
    int idx = ((kt * 8 + (nt >> 1)) * 32 + lane) * 2 + (nt & 1);
    g_Bh[idx] = ((u64)pack_hf2(h2, h3) << 32) | pack_hf2(h0, h1);
}

__device__ __forceinline__ void conv_store(char* smem, u32 base, int row,
                                           int lane, float4 a, float4 b,
                                           bool valid) {
    u64 hp = 0;
    if (valid) {
        float h0 = fmaxf(a.x * b.x, 0.f), h1 = fmaxf(a.y * b.y, 0.f);
        float h2 = fmaxf(a.z * b.z, 0.f), h3 = fmaxf(a.w * b.w, 0.f);
        u32 hi01 = pack_hf2(__float2half(h0), __float2half(h1));
        u32 hi23 = pack_hf2(__float2half(h2), __float2half(h3));
        hp = ((u64)hi23 << 32) | hi01;
    }
    u32 off = (u32)row * A_PITCH + (u32)lane * 8;
    *(u64*)(smem + base + off) = hp;
}

__global__ void __launch_bounds__(NTHREADS, 1)
vgae_mma_kernel(const float* __restrict__ x,
                const float* __restrict__ b1g,
                const float* __restrict__ W2,
                const float* __restrict__ b2g,
                const int*   __restrict__ ei_pos,
                const int*   __restrict__ ei_neg,
                float*       __restrict__ out,
                int E, int total, int n_tiles)
{
    extern __shared__ char smem[];
    float* sB1  = (float*)(smem + SM_MISC);          // 128 f32
    float* sW2  = (float*)(smem + SM_MISC + 512);    // 128 f32
    float* sRed = (float*)(smem + SM_MISC + 1024);   // [3][128][2] f32

    const int tid  = threadIdx.x;
    const int wid  = tid >> 5;
    const int lane = tid & 31;
    const u32 sbase = smem_u32(smem);

    {
        u64* bh = (u64*)(smem + SM_B);
        #pragma unroll 4
        for (int i = tid; i < 4096; i += NTHREADS) bh[i] = g_Bh[i];
        if (tid < 128) { sB1[tid] = b1g[tid]; sW2[tid] = W2[tid]; }
    }
    const float b2v = __ldg(b2g);
    __syncthreads();     // B + bias visible to all; last CTA-wide barrier

    const bool is_prod = (wid < 8);
    const int r0 = (wid & 7) * 16;   // producer rows r0..r0+15
    const int nit = (n_tiles > (int)blockIdx.x)
                  ? (n_tiles - blockIdx.x + gridDim.x - 1) / gridDim.x : 0;

    #define LOAD_IDX(T, IDXV) do {                                           \
        (IDXV) = 0;                                                          \
        int _e0 = (T) * TILE_E + r0;                                         \
        const int* _ei = ei_pos; int _el = _e0;                              \
        if (_el >= E) { _ei = ei_neg; _el -= E; }                            \
        if (_e0 + (lane & 15) < total)                                       \
            (IDXV) = __ldg(_ei + _el + (lane & 15) + ((lane >= 16) ? E : 0));\
    } while (0)

    #define FETCH_ROW(IDXV, J, A4, B4, VAL, TBASE) do {                      \
        (VAL) = ((TBASE) + r0 + (J)) < total;                                \
        int _u = __shfl_sync(0xffffffffu, (IDXV), (J));                      \
        int _v = __shfl_sync(0xffffffffu, (IDXV), (J) + 16);                 \
        (A4) = ldg_na(x + (size_t)_u * 128 + lane * 4);                      \
        (B4) = ldg_na(x + (size_t)_v * 128 + lane * 4);                      \
    } while (0)

    #define GATHER16(IDXV, BASE, TBASE) do {                                 \
        _Pragma("unroll")                                                    \
        for (int w = 0; w < 2; ++w) {                                        \
            float4 xa[8], xb[8]; bool vv[8];                                 \
            _Pragma("unroll")                                                \
            for (int j = 0; j < 8; ++j)                                      \
                FETCH_ROW(IDXV, w * 8 + j, xa[j], xb[j], vv[j], TBASE);      \
            _Pragma("unroll")                                                \
            for (int j = 0; j < 8; ++j)                                      \
                conv_store(smem, BASE, r0 + w * 8 + j, lane, xa[j], xb[j],   \
                           vv[j]);                                           \
        }                                                                    \
    } while (0)

    if (is_prod) {
        // ==================== PRODUCER WARPS ====================
        int i = 0;
        for (int tile = blockIdx.x; tile < n_tiles; tile += gridDim.x, ++i) {
            int b = i % NBUF;
            if (i >= NBUF) {
                NB_SYNC(4 + b);                    // consumers freed buffer b
                // deferred epilogue STG for tile i-NBUF (results in sRed[b])
                if (tid < TILE_E) {
                    int e = (tile - NBUF * (int)gridDim.x) * TILE_E + tid;
                    if (e < total) {
                        const float* rp = sRed + b * 256 + tid * 2;
                        float s = rp[0] + rp[1] + b2v;
                        out[e] = 1.f / (1.f + expf(-s));
                    }
                }
            }
            int idxv; LOAD_IDX(tile, idxv);
            GATHER16(idxv, SM_A + (u32)b * A_BUF, tile * TILE_E);
            NB_ARRIVE(1 + b);                      // buffer b full
        }
        // drain: STG for the last min(NBUF, nit) tiles
        int j0 = (nit >= NBUF) ? nit - NBUF : 0;
        for (int j = j0; j < nit; ++j) {
            int b = j % NBUF;
            NB_SYNC(4 + b);
            if (tid < TILE_E) {
                int e = ((int)blockIdx.x + j * (int)gridDim.x) * TILE_E + tid;
                if (e < total) {
                    const float* rp = sRed + b * 256 + tid * 2;
                    float s = rp[0] + rp[1] + b2v;
                    out[e] = 1.f / (1.f + expf(-s));
                }
            }
        }
    } else {
        // ==================== CONSUMER WARPS ====================
        const int cw = wid - 8;
        const int wm = cw & 3;           // 32-row m-strip
        const int wn = cw >> 2;          // 64-col n-strip
        const u32 a_lm0 = (u32)(wm * 32 + (lane & 15)) * A_PITCH
                        + (u32)(lane >> 4) * 16;

        int i = 0;
        for (int tile = blockIdx.x; tile < n_tiles; tile += gridDim.x, ++i) {
            int b = i % NBUF;
            NB_SYNC(1 + b);                        // buffer b full

            const u32 a_lm = sbase + SM_A + (u32)b * A_BUF + a_lm0;
            float acc[2][8][4];
            #pragma unroll
            for (int mf = 0; mf < 2; ++mf)
                #pragma unroll
                for (int nt = 0; nt < 8; ++nt)
                    #pragma unroll
                    for (int c = 0; c < 4; ++c) acc[mf][nt][c] = 0.f;

            #pragma unroll
            for (int kt = 0; kt < 8; ++kt) {
                u32 ah[2][4];
                #pragma unroll
                for (int mf = 0; mf < 2; ++mf)
                    ldmatrix_x4(ah[mf],
                                a_lm + (u32)mf * (16 * A_PITCH) + (u32)kt * 32);
                u32 bq[8][2];
                #pragma unroll
                for (int np = 0; np < 4; ++np) {
                    u32 boff = (u32)(((kt * 8 + wn * 4 + np) * 32 + lane)
                                     * 16);
                    uint4 q = *(const uint4*)(smem + SM_B + boff);
                    bq[np*2][0] = q.x; bq[np*2][1] = q.y;
                    bq[np*2+1][0] = q.z; bq[np*2+1][1] = q.w;
                }
                #pragma unroll
                for (int mf = 0; mf < 2; ++mf)
                    #pragma unroll
                    for (int nt = 0; nt < 8; ++nt)
                        mma_fp16(acc[mf][nt], ah[mf], bq[nt]);
            }

            // partial epilogue -> sRed[b]
            #pragma unroll
            for (int mf = 0; mf < 2; ++mf) {
                float p0 = 0.f, p1 = 0.f;
                #pragma unroll
                for (int nt = 0; nt < 8; ++nt) {
                    int n = wn * 64 + nt * 8 + (lane & 3) * 2;
                    float bia0 = sB1[n], bia1 = sB1[n + 1];
                    float w20  = sW2[n], w21  = sW2[n + 1];
                    p0 = fmaf(fmaxf(acc[mf][nt][0] + bia0, 0.f), w20, p0);
                    p0 = fmaf(fmaxf(acc[mf][nt][1] + bia1, 0.f), w21, p0);
                    p1 = fmaf(fmaxf(acc[mf][nt][2] + bia0, 0.f), w20, p1);
                    p1 = fmaf(fmaxf(acc[mf][nt][3] + bia1, 0.f), w21, p1);
                }
                p0 += __shfl_xor_sync(0xffffffffu, p0, 1);
                p0 += __shfl_xor_sync(0xffffffffu, p0, 2);
                p1 += __shfl_xor_sync(0xffffffffu, p1, 1);
                p1 += __shfl_xor_sync(0xffffffffu, p1, 2);
                if ((lane & 3) == 0) {
                    int rr = wm * 32 + mf * 16 + (lane >> 2);
                    float* rb = sRed + b * 256;
                    rb[rr * 2 + wn] = p0;
                    rb[(rr + 8) * 2 + wn] = p1;
                }
            }
            NB_ARRIVE(4 + b);                      // buffer b free + sRed ready
        }
    }
    #undef LOAD_IDX
    #undef FETCH_ROW
    #undef GATHER16
}

// ---------------------------------------------------------------------------
extern "C" void kernel_launch(void* const* d_in, const int* in_sizes, int n_in,
                              void* d_out, int out_size)
{
    const float* x  = (const float*)d_in[0];
    const float* W1 = (const float*)d_in[1];
    const float* b1 = (const float*)d_in[2];
    const float* W2 = (const float*)d_in[3];
    const float* b2 = (const float*)d_in[4];
    const int* eip  = (const int*)d_in[5];
    const int* ein  = (const int*)d_in[6];
    float* out = (float*)d_out;

    int E       = in_sizes[5] / 2;
    int total   = out_size;
    int n_tiles = (total + TILE_E - 1) / TILE_E;

    prep_kernel<<<16, 256>>>(W1);

    cudaFuncSetAttribute(vgae_mma_kernel,
                         cudaFuncAttributeMaxDynamicSharedMemorySize, SMEM_TOTAL);
    int grid = 148;
    if (grid > n_tiles) grid = n_tiles;
    vgae_mma_kernel<<<grid, NTHREADS, SMEM_TOTAL>>>(x, b1, W2, b2, eip, ein,
                                                    out, E, total, n_tiles);
}

// round 12
// speedup vs baseline: 8.3168x; 1.0298x over previous
#include <cuda_runtime.h>
#include <cuda_fp16.h>
#include <math.h>
#include <stdint.h>

typedef unsigned int u32;
typedef unsigned long long u64;

// ---------------------------------------------------------------------------
// vgae_decoder, warp-specialized single-pass fp16 mma:
//   D = fp16(xu)*fp16(xv) relu'd @ fp16(W1)   (fp32 accumulate)
// R12: x pre-converted to fp16 (g_xh) -> gather bytes halved (2wf/row-load);
//      producer convert is HMUL2/HMAX2. Triple-buffered A ring + split
//      named barriers retained from R11.
// ---------------------------------------------------------------------------

#define A_PITCH 272
#define SM_B   0
#define SM_A   32768
#define A_BUF  34816                     // one fp16 plane (128*272)
#define NBUF   3
#define SM_MISC (SM_A + NBUF * A_BUF)    // 137216
#define SMEM_TOTAL (SM_MISC + 4608)
#define NTHREADS 512
#define TILE_E 128
#define MAX_NODES 100000

__device__ u64 g_Bh[4096];               // fp16 W1 fragments, mma order
__device__ u64 g_xh[MAX_NODES * 32];     // fp16 x, 32 u64 (=128 halfs) per row

#define NB_ARRIVE(id) asm volatile("bar.arrive %0, 512;" :: "r"(id) : "memory")
#define NB_SYNC(id)   asm volatile("bar.sync %0, 512;"   :: "r"(id) : "memory")

__device__ __forceinline__ u32 pack_hf2(__half a, __half b) {
    __half2 t; t.x = a; t.y = b; return *(u32*)&t;
}
__device__ __forceinline__ u32 smem_u32(const void* p) {
    u32 a; asm("{ .reg .u64 t; cvta.to.shared.u64 t, %1; cvt.u32.u64 %0, t; }"
               : "=r"(a) : "l"(p)); return a;
}
__device__ __forceinline__ void ldmatrix_x4(u32* r, u32 saddr) {
    asm volatile("ldmatrix.sync.aligned.m8n8.x4.shared.b16 {%0,%1,%2,%3}, [%4];"
                 : "=r"(r[0]), "=r"(r[1]), "=r"(r[2]), "=r"(r[3]) : "r"(saddr));
}
__device__ __forceinline__ void mma_fp16(float* d, const u32* a, const u32* b) {
    asm volatile(
        "mma.sync.aligned.m16n8k16.row.col.f32.f16.f16.f32 "
        "{%0,%1,%2,%3}, {%4,%5,%6,%7}, {%8,%9}, {%0,%1,%2,%3};"
        : "+f"(d[0]), "+f"(d[1]), "+f"(d[2]), "+f"(d[3])
        : "r"(a[0]), "r"(a[1]), "r"(a[2]), "r"(a[3]), "r"(b[0]), "r"(b[1]));
}

// ---- prep: W1 -> fp16 fragments ----
__global__ void prep_kernel(const float* __restrict__ W1) {
    int t = blockIdx.x * blockDim.x + threadIdx.x;
    if (t >= 4096) return;
    int lane = t & 31, nt = (t >> 5) & 15, kt = t >> 9;
    int n  = nt * 8 + (lane >> 2);
    int k0 = kt * 16 + (lane & 3) * 2;
    __half h0 = __float2half(W1[(k0    ) * 128 + n]);
    __half h1 = __float2half(W1[(k0 + 1) * 128 + n]);
    __half h2 = __float2half(W1[(k0 + 8) * 128 + n]);
    __half h3 = __float2half(W1[(k0 + 9) * 128 + n]);
    int idx = ((kt * 8 + (nt >> 1)) * 32 + lane) * 2 + (nt & 1);
    g_Bh[idx] = ((u64)pack_hf2(h2, h3) << 32) | pack_hf2(h0, h1);
}

// ---- prep: x -> fp16 (4 floats -> 1 u64 per thread) ----
__global__ void prep_x_kernel(const float* __restrict__ x, int n4) {
    int i = blockIdx.x * blockDim.x + threadIdx.x;
    if (i >= n4) return;
    float4 v = ((const float4*)x)[i];
    __half2 h0 = __floats2half2_rn(v.x, v.y);
    __half2 h1 = __floats2half2_rn(v.z, v.w);
    u64 p;
    ((__half2*)&p)[0] = h0;
    ((__half2*)&p)[1] = h1;
    g_xh[i] = p;
}

// relu(xu*xv) in fp16, store 4 halfs (u64) to smem
__device__ __forceinline__ void conv_store(char* smem, u32 base, int row,
                                           int lane, u64 ua, u64 ub,
                                           bool valid) {
    u64 hp = 0;
    if (valid) {
        __half2 z = __float2half2_rn(0.f);
        __half2 h0 = __hmax2(__hmul2(((__half2*)&ua)[0], ((__half2*)&ub)[0]), z);
        __half2 h1 = __hmax2(__hmul2(((__half2*)&ua)[1], ((__half2*)&ub)[1]), z);
        ((__half2*)&hp)[0] = h0;
        ((__half2*)&hp)[1] = h1;
    }
    u32 off = (u32)row * A_PITCH + (u32)lane * 8;
    *(u64*)(smem + base + off) = hp;
}

__global__ void __launch_bounds__(NTHREADS, 1)
vgae_mma_kernel(const float* __restrict__ b1g,
                const float* __restrict__ W2,
                const float* __restrict__ b2g,
                const int*   __restrict__ ei_pos,
                const int*   __restrict__ ei_neg,
                float*       __restrict__ out,
                int E, int total, int n_tiles)
{
    extern __shared__ char smem[];
    float* sB1  = (float*)(smem + SM_MISC);          // 128 f32
    float* sW2  = (float*)(smem + SM_MISC + 512);    // 128 f32
    float* sRed = (float*)(smem + SM_MISC + 1024);   // [3][128][2] f32

    const int tid  = threadIdx.x;
    const int wid  = tid >> 5;
    const int lane = tid & 31;
    const u32 sbase = smem_u32(smem);

    {
        u64* bh = (u64*)(smem + SM_B);
        #pragma unroll 4
        for (int i = tid; i < 4096; i += NTHREADS) bh[i] = g_Bh[i];
        if (tid < 128) { sB1[tid] = b1g[tid]; sW2[tid] = W2[tid]; }
    }
    const float b2v = __ldg(b2g);
    __syncthreads();

    const bool is_prod = (wid < 8);
    const int r0 = (wid & 7) * 16;
    const int nit = (n_tiles > (int)blockIdx.x)
                  ? (n_tiles - blockIdx.x + gridDim.x - 1) / gridDim.x : 0;

    #define LOAD_IDX(T, IDXV) do {                                           \
        (IDXV) = 0;                                                          \
        int _e0 = (T) * TILE_E + r0;                                         \
        const int* _ei = ei_pos; int _el = _e0;                              \
        if (_el >= E) { _ei = ei_neg; _el -= E; }                            \
        if (_e0 + (lane & 15) < total)                                       \
            (IDXV) = __ldg(_ei + _el + (lane & 15) + ((lane >= 16) ? E : 0));\
    } while (0)

    #define FETCH_ROW(IDXV, J, UA, UB, VAL, TBASE) do {                      \
        (VAL) = ((TBASE) + r0 + (J)) < total;                                \
        int _u = __shfl_sync(0xffffffffu, (IDXV), (J));                      \
        int _v = __shfl_sync(0xffffffffu, (IDXV), (J) + 16);                 \
        (UA) = __ldg(g_xh + (size_t)_u * 32 + lane);                         \
        (UB) = __ldg(g_xh + (size_t)_v * 32 + lane);                         \
    } while (0)

    #define GATHER16(IDXV, BASE, TBASE) do {                                 \
        _Pragma("unroll")                                                    \
        for (int w = 0; w < 2; ++w) {                                        \
            u64 xa[8], xb[8]; bool vv[8];                                    \
            _Pragma("unroll")                                                \
            for (int j = 0; j < 8; ++j)                                      \
                FETCH_ROW(IDXV, w * 8 + j, xa[j], xb[j], vv[j], TBASE);      \
            _Pragma("unroll")                                                \
            for (int j = 0; j < 8; ++j)                                      \
                conv_store(smem, BASE, r0 + w * 8 + j, lane, xa[j], xb[j],   \
                           vv[j]);                                           \
        }                                                                    \
    } while (0)

    if (is_prod) {
        // ==================== PRODUCER WARPS ====================
        int i = 0;
        for (int tile = blockIdx.x; tile < n_tiles; tile += gridDim.x, ++i) {
            int b = i % NBUF;
            if (i >= NBUF) {
                NB_SYNC(4 + b);
                if (tid < TILE_E) {
                    int e = (tile - NBUF * (int)gridDim.x) * TILE_E + tid;
                    if (e < total) {
                        const float* rp = sRed + b * 256 + tid * 2;
                        float s = rp[0] + rp[1] + b2v;
                        out[e] = 1.f / (1.f + expf(-s));
                    }
                }
            }
            int idxv; LOAD_IDX(tile, idxv);
            GATHER16(idxv, SM_A + (u32)b * A_BUF, tile * TILE_E);
            NB_ARRIVE(1 + b);
        }
        int j0 = (nit >= NBUF) ? nit - NBUF : 0;
        for (int j = j0; j < nit; ++j) {
            int b = j % NBUF;
            NB_SYNC(4 + b);
            if (tid < TILE_E) {
                int e = ((int)blockIdx.x + j * (int)gridDim.x) * TILE_E + tid;
                if (e < total) {
                    const float* rp = sRed + b * 256 + tid * 2;
                    float s = rp[0] + rp[1] + b2v;
                    out[e] = 1.f / (1.f + expf(-s));
                }
            }
        }
    } else {
        // ==================== CONSUMER WARPS ====================
        const int cw = wid - 8;
        const int wm = cw & 3;
        const int wn = cw >> 2;
        const u32 a_lm0 = (u32)(wm * 32 + (lane & 15)) * A_PITCH
                        + (u32)(lane >> 4) * 16;

        int i = 0;
        for (int tile = blockIdx.x; tile < n_tiles; tile += gridDim.x, ++i) {
            int b = i % NBUF;
            NB_SYNC(1 + b);

            const u32 a_lm = sbase + SM_A + (u32)b * A_BUF + a_lm0;
            float acc[2][8][4];
            #pragma unroll
            for (int mf = 0; mf < 2; ++mf)
                #pragma unroll
                for (int nt = 0; nt < 8; ++nt)
                    #pragma unroll
                    for (int c = 0; c < 4; ++c) acc[mf][nt][c] = 0.f;

            #pragma unroll
            for (int kt = 0; kt < 8; ++kt) {
                u32 ah[2][4];
                #pragma unroll
                for (int mf = 0; mf < 2; ++mf)
                    ldmatrix_x4(ah[mf],
                                a_lm + (u32)mf * (16 * A_PITCH) + (u32)kt * 32);
                u32 bq[8][2];
                #pragma unroll
                for (int np = 0; np < 4; ++np) {
                    u32 boff = (u32)(((kt * 8 + wn * 4 + np) * 32 + lane)
                                     * 16);
                    uint4 q = *(const uint4*)(smem + SM_B + boff);
                    bq[np*2][0] = q.x; bq[np*2][1] = q.y;
                    bq[np*2+1][0] = q.z; bq[np*2+1][1] = q.w;
                }
                #pragma unroll
                for (int mf = 0; mf < 2; ++mf)
                    #pragma unroll
                    for (int nt = 0; nt < 8; ++nt)
                        mma_fp16(acc[mf][nt], ah[mf], bq[nt]);
            }

            #pragma unroll
            for (int mf = 0; mf < 2; ++mf) {
                float p0 = 0.f, p1 = 0.f;
                #pragma unroll
                for (int nt = 0; nt < 8; ++nt) {
                    int n = wn * 64 + nt * 8 + (lane & 3) * 2;
                    float bia0 = sB1[n], bia1 = sB1[n + 1];
                    float w20  = sW2[n], w21  = sW2[n + 1];
                    p0 = fmaf(fmaxf(acc[mf][nt][0] + bia0, 0.f), w20, p0);
                    p0 = fmaf(fmaxf(acc[mf][nt][1] + bia1, 0.f), w21, p0);
                    p1 = fmaf(fmaxf(acc[mf][nt][2] + bia0, 0.f), w20, p1);
                    p1 = fmaf(fmaxf(acc[mf][nt][3] + bia1, 0.f), w21, p1);
                }
                p0 += __shfl_xor_sync(0xffffffffu, p0, 1);
                p0 += __shfl_xor_sync(0xffffffffu, p0, 2);
                p1 += __shfl_xor_sync(0xffffffffu, p1, 1);
                p1 += __shfl_xor_sync(0xffffffffu, p1, 2);
                if ((lane & 3) == 0) {
                    int rr = wm * 32 + mf * 16 + (lane >> 2);
                    float* rb = sRed + b * 256;
                    rb[rr * 2 + wn] = p0;
                    rb[(rr + 8) * 2 + wn] = p1;
                }
            }
            NB_ARRIVE(4 + b);
        }
    }
    #undef LOAD_IDX
    #undef FETCH_ROW
    #undef GATHER16
}

// ---------------------------------------------------------------------------
extern "C" void kernel_launch(void* const* d_in, const int* in_sizes, int n_in,
                              void* d_out, int out_size)
{
    const float* x  = (const float*)d_in[0];
    const float* W1 = (const float*)d_in[1];
    const float* b1 = (const float*)d_in[2];
    const float* W2 = (const float*)d_in[3];
    const float* b2 = (const float*)d_in[4];
    const int* eip  = (const int*)d_in[5];
    const int* ein  = (const int*)d_in[6];
    float* out = (float*)d_out;

    int E       = in_sizes[5] / 2;
    int total   = out_size;
    int n_tiles = (total + TILE_E - 1) / TILE_E;

    int n4 = in_sizes[0] / 4;                    // x element count / 4
    if (n4 > MAX_NODES * 32) n4 = MAX_NODES * 32;

    prep_kernel<<<16, 256>>>(W1);
    prep_x_kernel<<<(n4 + 255) / 256, 256>>>(x, n4);

    cudaFuncSetAttribute(vgae_mma_kernel,
                         cudaFuncAttributeMaxDynamicSharedMemorySize, SMEM_TOTAL);
    int grid = 148;
    if (grid > n_tiles) grid = n_tiles;
    vgae_mma_kernel<<<grid, NTHREADS, SMEM_TOTAL>>>(b1, W2, b2, eip, ein,
                                                    out, E, total, n_tiles);
}